// round 1
// baseline (speedup 1.0000x reference)
#include <cuda_runtime.h>
#include <math.h>
#include <stddef.h>

// Problem constants
// B=2, N=4096, C=512, HEAD=8, dh=64, SR=2, R=8, H=W=64, N_kv=1024
#define LN_EPS 1e-5f

// ---------------------------------------------------------------------------
// Scratch (static __device__ arrays; no dynamic allocation allowed)
// ---------------------------------------------------------------------------
__device__ float g_WqE[512 * 512];            // Wq + Aq@Bq
__device__ float g_WkvE[512 * 1024];          // Wkv with Av@Bv folded into both halves
__device__ float g_q[2 * 4096 * 512];         // q (B*N, C)
__device__ float g_xs[2 * 1024 * 512];        // conv output, then LN'd in place
__device__ float g_kv[2 * 1024 * 1024];       // kv (B*1024, 2C): k cols [0,512), v cols [512,1024)
__device__ float g_ao[2 * 4096 * 512];        // attention output (B*N, C)

// ---------------------------------------------------------------------------
// Weight prep: fold LoRA (rank 8) into dense weights
// ---------------------------------------------------------------------------
__global__ void prep_wq_kernel(const float* __restrict__ Wq,
                               const float* __restrict__ Aq,
                               const float* __restrict__ Bq,
                               float* __restrict__ Weff) {
    int idx = blockIdx.x * blockDim.x + threadIdx.x;   // 512*512
    int k = idx >> 9, n = idx & 511;
    float s = Wq[idx];
#pragma unroll
    for (int r = 0; r < 8; r++) s += Aq[k * 8 + r] * Bq[r * 512 + n];
    Weff[idx] = s;
}

__global__ void prep_wkv_kernel(const float* __restrict__ Wkv,
                                const float* __restrict__ Av,
                                const float* __restrict__ Bv,
                                float* __restrict__ Weff) {
    int idx = blockIdx.x * blockDim.x + threadIdx.x;   // 512*1024
    int k = idx >> 10, n = idx & 1023, ln = n & 511;
    float s = Wkv[idx];
#pragma unroll
    for (int r = 0; r < 8; r++) s += Av[k * 8 + r] * Bv[r * 512 + ln];
    Weff[idx] = s;
}

// ---------------------------------------------------------------------------
// Generic SGEMM: C[M,N] = A[M,K] @ W[K,N] + bias[N]
// Tile 64x64x16, 256 threads, 4x4 micro-tile, float4 smem loads.
// Requires M%64==0, N%64==0, K%16==0 (true for all call sites here).
// ---------------------------------------------------------------------------
__global__ void sgemm_kernel(const float* __restrict__ A,
                             const float* __restrict__ W,
                             const float* __restrict__ bias,
                             float* __restrict__ Cmat,
                             int M, int N, int K) {
    __shared__ __align__(16) float As[16][68];   // [k][m]
    __shared__ __align__(16) float Ws[16][68];   // [k][n]

    int tid = threadIdx.x;
    int tx = tid & 15, ty = tid >> 4;
    int m0 = blockIdx.x * 64, n0 = blockIdx.y * 64;

    float acc[4][4] = {};

    int arow = tid >> 2;            // 0..63
    int ak = (tid & 3) * 4;         // 0,4,8,12
    int wk = tid >> 4;              // 0..15
    int wc = (tid & 15) * 4;        // 0..60

    const float* Aptr = A + (size_t)(m0 + arow) * K + ak;
    const float* Wptr = W + (size_t)wk * N + n0 + wc;

    for (int k0 = 0; k0 < K; k0 += 16) {
        float4 av = *(const float4*)(Aptr + k0);
        As[ak + 0][arow] = av.x;
        As[ak + 1][arow] = av.y;
        As[ak + 2][arow] = av.z;
        As[ak + 3][arow] = av.w;
        *(float4*)&Ws[wk][wc] = *(const float4*)(Wptr + (size_t)k0 * N);
        __syncthreads();
#pragma unroll
        for (int kk = 0; kk < 16; kk++) {
            float4 a = *(const float4*)&As[kk][ty * 4];
            float4 w = *(const float4*)&Ws[kk][tx * 4];
            acc[0][0] += a.x * w.x; acc[0][1] += a.x * w.y; acc[0][2] += a.x * w.z; acc[0][3] += a.x * w.w;
            acc[1][0] += a.y * w.x; acc[1][1] += a.y * w.y; acc[1][2] += a.y * w.z; acc[1][3] += a.y * w.w;
            acc[2][0] += a.z * w.x; acc[2][1] += a.z * w.y; acc[2][2] += a.z * w.z; acc[2][3] += a.z * w.w;
            acc[3][0] += a.w * w.x; acc[3][1] += a.w * w.y; acc[3][2] += a.w * w.z; acc[3][3] += a.w * w.w;
        }
        __syncthreads();
    }

    float4 bv = *(const float4*)&bias[n0 + tx * 4];
#pragma unroll
    for (int i = 0; i < 4; i++) {
        float4 r;
        r.x = acc[i][0] + bv.x;
        r.y = acc[i][1] + bv.y;
        r.z = acc[i][2] + bv.z;
        r.w = acc[i][3] + bv.w;
        *(float4*)&Cmat[(size_t)(m0 + ty * 4 + i) * N + n0 + tx * 4] = r;
    }
}

// ---------------------------------------------------------------------------
// Conv (2x2, stride 2, VALID, NHWC/HWIO) as im2col GEMM:
//   xs[(b,oh,ow), :] = sum_p x[b, patchrow(p), :] @ Wsr_p + bsr
// A is gathered from x; W = Wsr viewed as (2048, 512) contiguous.
// M=2048, N=512, K=2048.
// ---------------------------------------------------------------------------
__global__ void conv_gemm_kernel(const float* __restrict__ x,
                                 const float* __restrict__ Wsr,
                                 const float* __restrict__ bsr,
                                 float* __restrict__ xs) {
    __shared__ __align__(16) float As[16][68];
    __shared__ __align__(16) float Ws[16][68];

    const int N = 512, K = 2048;
    int tid = threadIdx.x;
    int tx = tid & 15, ty = tid >> 4;
    int m0 = blockIdx.x * 64, n0 = blockIdx.y * 64;

    float acc[4][4] = {};

    int arow = tid >> 2;
    int ak = (tid & 3) * 4;
    int wk = tid >> 4;
    int wc = (tid & 15) * 4;

    int m = m0 + arow;
    int b = m >> 10;
    int s = m & 1023;
    int oh = s >> 5, ow = s & 31;
    const float* xb = x + (size_t)b * 4096 * 512;
    int base_n = (oh * 2) * 64 + ow * 2;

    const float* Wptr = Wsr + (size_t)wk * N + n0 + wc;

    for (int k0 = 0; k0 < K; k0 += 16) {
        int kg = k0 + ak;
        int p = kg >> 9;
        int c = kg & 511;
        int roff = base_n + ((p >> 1) << 6) + (p & 1);
        float4 av = *(const float4*)(xb + (size_t)roff * 512 + c);
        As[ak + 0][arow] = av.x;
        As[ak + 1][arow] = av.y;
        As[ak + 2][arow] = av.z;
        As[ak + 3][arow] = av.w;
        *(float4*)&Ws[wk][wc] = *(const float4*)(Wptr + (size_t)k0 * N);
        __syncthreads();
#pragma unroll
        for (int kk = 0; kk < 16; kk++) {
            float4 a = *(const float4*)&As[kk][ty * 4];
            float4 w = *(const float4*)&Ws[kk][tx * 4];
            acc[0][0] += a.x * w.x; acc[0][1] += a.x * w.y; acc[0][2] += a.x * w.z; acc[0][3] += a.x * w.w;
            acc[1][0] += a.y * w.x; acc[1][1] += a.y * w.y; acc[1][2] += a.y * w.z; acc[1][3] += a.y * w.w;
            acc[2][0] += a.z * w.x; acc[2][1] += a.z * w.y; acc[2][2] += a.z * w.z; acc[2][3] += a.z * w.w;
            acc[3][0] += a.w * w.x; acc[3][1] += a.w * w.y; acc[3][2] += a.w * w.z; acc[3][3] += a.w * w.w;
        }
        __syncthreads();
    }

    float4 bv = *(const float4*)&bsr[n0 + tx * 4];
#pragma unroll
    for (int i = 0; i < 4; i++) {
        float4 r;
        r.x = acc[i][0] + bv.x;
        r.y = acc[i][1] + bv.y;
        r.z = acc[i][2] + bv.z;
        r.w = acc[i][3] + bv.w;
        *(float4*)&xs[(size_t)(m0 + ty * 4 + i) * N + n0 + tx * 4] = r;
    }
}

// ---------------------------------------------------------------------------
// LayerNorm over C=512 in place, one block (256 threads) per row
// ---------------------------------------------------------------------------
__global__ void ln_kernel(float* __restrict__ xs,
                          const float* __restrict__ gamma,
                          const float* __restrict__ beta) {
    __shared__ float red[256];
    __shared__ float s_mean, s_inv;
    int t = threadIdx.x;
    float* p = xs + (size_t)blockIdx.x * 512;
    float v0 = p[t], v1 = p[t + 256];
    red[t] = v0 + v1;
    __syncthreads();
    for (int off = 128; off; off >>= 1) {
        if (t < off) red[t] += red[t + off];
        __syncthreads();
    }
    if (t == 0) s_mean = red[0] * (1.f / 512.f);
    __syncthreads();
    float mean = s_mean;
    float d0 = v0 - mean, d1 = v1 - mean;
    red[t] = d0 * d0 + d1 * d1;
    __syncthreads();
    for (int off = 128; off; off >>= 1) {
        if (t < off) red[t] += red[t + off];
        __syncthreads();
    }
    if (t == 0) s_inv = rsqrtf(red[0] * (1.f / 512.f) + LN_EPS);
    __syncthreads();
    float inv = s_inv;
    p[t]       = d0 * inv * gamma[t]       + beta[t];
    p[t + 256] = d1 * inv * gamma[t + 256] + beta[t + 256];
}

// ---------------------------------------------------------------------------
// Fused flash attention: per block = (64 q rows, head h, batch b)
// K/V share one smem tile; online softmax. dh=64, N_kv=1024 (16 tiles of 64).
//   Qs: transposed [d][row], KVs: K transposed [d][col] then V [row][col],
//   Ss: P transposed [col][row] so P@V reads are float4.
// ---------------------------------------------------------------------------
#define ATTN_SMEM_FLOATS (3 * 64 * 68 + 3 * 64)

__global__ void attn_kernel(const float* __restrict__ q,
                            const float* __restrict__ kv,
                            float* __restrict__ ao) {
    extern __shared__ __align__(16) float sm[];
    float* Qs  = sm;                 // 64*68
    float* KVs = Qs + 64 * 68;       // 64*68
    float* Ss  = KVs + 64 * 68;      // 64*68
    float* m_s = Ss + 64 * 68;       // 64
    float* l_s = m_s + 64;           // 64
    float* cf  = l_s + 64;           // 64

    int tid = threadIdx.x;
    int tx = tid & 15, ty = tid >> 4;
    int b = blockIdx.z, h = blockIdx.y;
    int q0 = blockIdx.x * 64;

    const float* qb = q + ((size_t)b * 4096 + q0) * 512 + h * 64;
    const float* kb = kv + (size_t)b * 1024 * 1024 + h * 64;
    const float* vb = kb + 512;

#pragma unroll
    for (int l = 0; l < 16; l++) {
        int e = tid + l * 256;
        int r = e >> 6, c = e & 63;
        Qs[c * 68 + r] = qb[(size_t)r * 512 + c];
    }
    if (tid < 64) { m_s[tid] = -3.0e38f; l_s[tid] = 0.f; }
    float o[4][4] = {};
    __syncthreads();

    for (int kbk = 0; kbk < 16; kbk++) {
        // --- load K tile (transposed) ---
        const float* kt = kb + (size_t)kbk * 64 * 1024;
#pragma unroll
        for (int l = 0; l < 16; l++) {
            int e = tid + l * 256;
            int r = e >> 6, c = e & 63;
            KVs[c * 68 + r] = kt[(size_t)r * 1024 + c];
        }
        __syncthreads();

        // --- S = Q K^T (micro 4x4) ---
        float s_[4][4] = {};
#pragma unroll
        for (int d = 0; d < 64; d++) {
            float4 a  = *(const float4*)&Qs[d * 68 + ty * 4];
            float4 bb = *(const float4*)&KVs[d * 68 + tx * 4];
            s_[0][0] += a.x * bb.x; s_[0][1] += a.x * bb.y; s_[0][2] += a.x * bb.z; s_[0][3] += a.x * bb.w;
            s_[1][0] += a.y * bb.x; s_[1][1] += a.y * bb.y; s_[1][2] += a.y * bb.z; s_[1][3] += a.y * bb.w;
            s_[2][0] += a.z * bb.x; s_[2][1] += a.z * bb.y; s_[2][2] += a.z * bb.z; s_[2][3] += a.z * bb.w;
            s_[3][0] += a.w * bb.x; s_[3][1] += a.w * bb.y; s_[3][2] += a.w * bb.z; s_[3][3] += a.w * bb.w;
        }
        // store S^T (scaled) into Ss[col][row]
#pragma unroll
        for (int j = 0; j < 4; j++) {
            float4 v;
            v.x = s_[0][j] * 0.125f;
            v.y = s_[1][j] * 0.125f;
            v.z = s_[2][j] * 0.125f;
            v.w = s_[3][j] * 0.125f;
            *(float4*)&Ss[(tx * 4 + j) * 68 + ty * 4] = v;
        }
        __syncthreads();

        // --- online softmax per row (threads 0..63) ---
        if (tid < 64) {
            float mold = m_s[tid];
            float tmax = mold;
#pragma unroll 8
            for (int c = 0; c < 64; c++) tmax = fmaxf(tmax, Ss[c * 68 + tid]);
            float corr = __expf(mold - tmax);
            float lsum = 0.f;
#pragma unroll 8
            for (int c = 0; c < 64; c++) {
                float e = __expf(Ss[c * 68 + tid] - tmax);
                Ss[c * 68 + tid] = e;
                lsum += e;
            }
            l_s[tid] = l_s[tid] * corr + lsum;
            m_s[tid] = tmax;
            cf[tid] = corr;
        }

        // --- load V tile (normal layout) into the K buffer ---
        const float* vt = vb + (size_t)kbk * 64 * 1024;
#pragma unroll
        for (int l = 0; l < 16; l++) {
            int e = tid + l * 256;
            int r = e >> 6, c = e & 63;
            KVs[r * 68 + c] = vt[(size_t)r * 1024 + c];
        }
        __syncthreads();

        // --- rescale O, accumulate O += P @ V ---
        float c0 = cf[ty * 4 + 0], c1 = cf[ty * 4 + 1];
        float c2 = cf[ty * 4 + 2], c3 = cf[ty * 4 + 3];
#pragma unroll
        for (int j = 0; j < 4; j++) {
            o[0][j] *= c0; o[1][j] *= c1; o[2][j] *= c2; o[3][j] *= c3;
        }
#pragma unroll
        for (int r = 0; r < 64; r++) {
            float4 pv = *(const float4*)&Ss[r * 68 + ty * 4];
            float4 vv = *(const float4*)&KVs[r * 68 + tx * 4];
            o[0][0] += pv.x * vv.x; o[0][1] += pv.x * vv.y; o[0][2] += pv.x * vv.z; o[0][3] += pv.x * vv.w;
            o[1][0] += pv.y * vv.x; o[1][1] += pv.y * vv.y; o[1][2] += pv.y * vv.z; o[1][3] += pv.y * vv.w;
            o[2][0] += pv.z * vv.x; o[2][1] += pv.z * vv.y; o[2][2] += pv.z * vv.z; o[2][3] += pv.z * vv.w;
            o[3][0] += pv.w * vv.x; o[3][1] += pv.w * vv.y; o[3][2] += pv.w * vv.z; o[3][3] += pv.w * vv.w;
        }
        __syncthreads();
    }

    // --- epilogue: divide by l, write out ---
    float* ob = ao + ((size_t)b * 4096 + q0) * 512 + h * 64;
#pragma unroll
    for (int i = 0; i < 4; i++) {
        float inv = 1.f / l_s[ty * 4 + i];
        float4 r;
        r.x = o[i][0] * inv;
        r.y = o[i][1] * inv;
        r.z = o[i][2] * inv;
        r.w = o[i][3] * inv;
        *(float4*)&ob[(size_t)(ty * 4 + i) * 512 + tx * 4] = r;
    }
}

// ---------------------------------------------------------------------------
// Launch
// ---------------------------------------------------------------------------
extern "C" void kernel_launch(void* const* d_in, const int* in_sizes, int n_in,
                              void* d_out, int out_size) {
    (void)in_sizes; (void)n_in; (void)out_size;

    const float* x     = (const float*)d_in[0];
    const float* Wq    = (const float*)d_in[1];
    const float* bq    = (const float*)d_in[2];
    const float* Wkv   = (const float*)d_in[3];
    const float* bkv   = (const float*)d_in[4];
    const float* Wproj = (const float*)d_in[5];
    const float* bproj = (const float*)d_in[6];
    const float* Aq    = (const float*)d_in[7];
    const float* Bq    = (const float*)d_in[8];
    const float* Av    = (const float*)d_in[9];
    const float* Bv    = (const float*)d_in[10];
    const float* Wsr   = (const float*)d_in[11];
    const float* bsr   = (const float*)d_in[12];
    const float* gamma = (const float*)d_in[13];
    const float* beta  = (const float*)d_in[14];
    float* out = (float*)d_out;

    float *WqE, *WkvE, *qbuf, *xs, *kvbuf, *ao;
    cudaGetSymbolAddress((void**)&WqE,  g_WqE);
    cudaGetSymbolAddress((void**)&WkvE, g_WkvE);
    cudaGetSymbolAddress((void**)&qbuf, g_q);
    cudaGetSymbolAddress((void**)&xs,   g_xs);
    cudaGetSymbolAddress((void**)&kvbuf,g_kv);
    cudaGetSymbolAddress((void**)&ao,   g_ao);

    // 1) fold LoRA into weights
    prep_wq_kernel<<<1024, 256>>>(Wq, Aq, Bq, WqE);
    prep_wkv_kernel<<<2048, 256>>>(Wkv, Av, Bv, WkvE);

    // 2) q = x @ WqE + bq          (M=8192, N=512, K=512)
    sgemm_kernel<<<dim3(128, 8), 256>>>(x, WqE, bq, qbuf, 8192, 512, 512);

    // 3) conv as im2col GEMM       (M=2048, N=512, K=2048)
    conv_gemm_kernel<<<dim3(32, 8), 256>>>(x, Wsr, bsr, xs);

    // 4) LayerNorm in place
    ln_kernel<<<2048, 256>>>(xs, gamma, beta);

    // 5) kv = xs @ WkvE + bkv      (M=2048, N=1024, K=512)
    sgemm_kernel<<<dim3(32, 16), 256>>>(xs, WkvE, bkv, kvbuf, 2048, 1024, 512);

    // 6) fused flash attention     (grid: 64 q-tiles x 8 heads x 2 batch)
    size_t attn_smem = ATTN_SMEM_FLOATS * sizeof(float);
    cudaFuncSetAttribute(attn_kernel, cudaFuncAttributeMaxDynamicSharedMemorySize,
                         (int)attn_smem);
    attn_kernel<<<dim3(64, 8, 2), 256, attn_smem>>>(qbuf, kvbuf, ao);

    // 7) out = ao @ Wproj + bproj  (M=8192, N=512, K=512)
    sgemm_kernel<<<dim3(128, 8), 256>>>(ao, Wproj, bproj, out, 8192, 512, 512);
}

// round 2
// speedup vs baseline: 1.1440x; 1.1440x over previous
#include <cuda_runtime.h>
#include <math.h>
#include <stddef.h>

#define LN_EPS 1e-5f
#define LOG2E 1.44269504088896340736f

// ---------------------------------------------------------------------------
// Scratch
// ---------------------------------------------------------------------------
__device__ float g_WqE[512 * 512];
__device__ float g_WkvE[512 * 1024];
__device__ float g_q[2 * 4096 * 512];
__device__ float g_xs[2 * 1024 * 512];
__device__ float g_kv[2 * 1024 * 1024];     // k cols [0,512), v cols [512,1024)
__device__ float g_kT[16 * 64 * 1024];      // K transposed: [b*8+h][d][token]
__device__ float g_convp[4 * 2048 * 512];   // conv partials per patch position
__device__ float g_ao[2 * 4096 * 512];

// ---------------------------------------------------------------------------
// LoRA fold
// ---------------------------------------------------------------------------
__global__ void prep_wq_kernel(const float* __restrict__ Wq,
                               const float* __restrict__ Aq,
                               const float* __restrict__ Bq,
                               float* __restrict__ Weff) {
    int idx = blockIdx.x * blockDim.x + threadIdx.x;
    int k = idx >> 9, n = idx & 511;
    float s = Wq[idx];
#pragma unroll
    for (int r = 0; r < 8; r++) s += Aq[k * 8 + r] * Bq[r * 512 + n];
    Weff[idx] = s;
}

__global__ void prep_wkv_kernel(const float* __restrict__ Wkv,
                                const float* __restrict__ Av,
                                const float* __restrict__ Bv,
                                float* __restrict__ Weff) {
    int idx = blockIdx.x * blockDim.x + threadIdx.x;
    int k = idx >> 10, n = idx & 1023, ln = n & 511;
    float s = Wkv[idx];
#pragma unroll
    for (int r = 0; r < 8; r++) s += Av[k * 8 + r] * Bv[r * 512 + ln];
    Weff[idx] = s;
}

// ---------------------------------------------------------------------------
// SGEMM 128x128x16, 256 threads, 8x8 micro, double-buffered smem.
// C[M,N] = A[M,K] @ W[K,N] + bias. M%128==0, N%128==0, K%16==0.
// ---------------------------------------------------------------------------
__global__ __launch_bounds__(256, 2)
void sgemm128_kernel(const float* __restrict__ A,
                     const float* __restrict__ W,
                     const float* __restrict__ bias,
                     float* __restrict__ Cmat,
                     int M, int N, int K) {
    __shared__ __align__(16) float As[2][16][132];
    __shared__ __align__(16) float Ws[2][16][128];

    int tid = threadIdx.x;
    int tx = tid & 15, ty = tid >> 4;
    int m0 = blockIdx.x * 128, n0 = blockIdx.y * 128;

    int arow = tid >> 1, ak = (tid & 1) * 8;
    int wrow = tid >> 4, wcol = (tid & 15) * 8;

    const float* Ap = A + (size_t)(m0 + arow) * K + ak;
    const float* Wp = W + (size_t)wrow * N + n0 + wcol;

    float acc[8][8] = {};
    int nk = K >> 4;

    // preload tile 0
    float4 a0 = *(const float4*)(Ap);
    float4 a1 = *(const float4*)(Ap + 4);
    float4 w0 = *(const float4*)(Wp);
    float4 w1 = *(const float4*)(Wp + 4);
    {
        float tmp[8] = {a0.x, a0.y, a0.z, a0.w, a1.x, a1.y, a1.z, a1.w};
#pragma unroll
        for (int j = 0; j < 8; j++) As[0][ak + j][arow] = tmp[j];
        *(float4*)&Ws[0][wrow][wcol] = w0;
        *(float4*)&Ws[0][wrow][wcol + 4] = w1;
    }
    __syncthreads();

    for (int kt = 0; kt < nk; kt++) {
        int cur = kt & 1;
        if (kt + 1 < nk) {
            const float* An = Ap + (kt + 1) * 16;
            const float* Wn = Wp + (size_t)(kt + 1) * 16 * N;
            a0 = *(const float4*)(An);
            a1 = *(const float4*)(An + 4);
            w0 = *(const float4*)(Wn);
            w1 = *(const float4*)(Wn + 4);
        }
#pragma unroll
        for (int kk = 0; kk < 16; kk++) {
            float av[8], bv[8];
            *(float4*)&av[0] = *(const float4*)&As[cur][kk][ty * 8];
            *(float4*)&av[4] = *(const float4*)&As[cur][kk][ty * 8 + 4];
            *(float4*)&bv[0] = *(const float4*)&Ws[cur][kk][tx * 8];
            *(float4*)&bv[4] = *(const float4*)&Ws[cur][kk][tx * 8 + 4];
#pragma unroll
            for (int i = 0; i < 8; i++)
#pragma unroll
                for (int j = 0; j < 8; j++)
                    acc[i][j] += av[i] * bv[j];
        }
        if (kt + 1 < nk) {
            int nxt = cur ^ 1;
            float tmp[8] = {a0.x, a0.y, a0.z, a0.w, a1.x, a1.y, a1.z, a1.w};
#pragma unroll
            for (int j = 0; j < 8; j++) As[nxt][ak + j][arow] = tmp[j];
            *(float4*)&Ws[nxt][wrow][wcol] = w0;
            *(float4*)&Ws[nxt][wrow][wcol + 4] = w1;
        }
        __syncthreads();
    }

    float4 b0 = *(const float4*)&bias[n0 + tx * 8];
    float4 b1 = *(const float4*)&bias[n0 + tx * 8 + 4];
#pragma unroll
    for (int i = 0; i < 8; i++) {
        float* cp = Cmat + (size_t)(m0 + ty * 8 + i) * N + n0 + tx * 8;
        float4 r0, r1;
        r0.x = acc[i][0] + b0.x; r0.y = acc[i][1] + b0.y;
        r0.z = acc[i][2] + b0.z; r0.w = acc[i][3] + b0.w;
        r1.x = acc[i][4] + b1.x; r1.y = acc[i][5] + b1.y;
        r1.z = acc[i][6] + b1.z; r1.w = acc[i][7] + b1.w;
        *(float4*)cp = r0;
        *(float4*)(cp + 4) = r1;
    }
}

// ---------------------------------------------------------------------------
// Conv split-K GEMM: blockIdx.z = patch position p (0..3).
// partial[p][m][n] = xrows_p[m] @ Wsr[p]  (K=512, no bias here)
// ---------------------------------------------------------------------------
__global__ __launch_bounds__(256, 2)
void conv_gemm_kernel(const float* __restrict__ x,
                      const float* __restrict__ Wsr,
                      float* __restrict__ part) {
    __shared__ __align__(16) float As[2][16][132];
    __shared__ __align__(16) float Ws[2][16][128];

    const int N = 512, K = 512;
    int tid = threadIdx.x;
    int tx = tid & 15, ty = tid >> 4;
    int m0 = blockIdx.x * 128, n0 = blockIdx.y * 128;
    int p = blockIdx.z;

    int arow = tid >> 1, ak = (tid & 1) * 8;
    int wrow = tid >> 4, wcol = (tid & 15) * 8;

    int m = m0 + arow;
    int b = m >> 10, s = m & 1023;
    int oh = s >> 5, ow = s & 31;
    int xr = (2 * oh + (p >> 1)) * 64 + 2 * ow + (p & 1);
    const float* Ap = x + ((size_t)b * 4096 + xr) * 512 + ak;
    const float* Wp = Wsr + (size_t)p * 512 * 512 + (size_t)wrow * N + n0 + wcol;

    float acc[8][8] = {};
    int nk = K >> 4;

    float4 a0 = *(const float4*)(Ap);
    float4 a1 = *(const float4*)(Ap + 4);
    float4 w0 = *(const float4*)(Wp);
    float4 w1 = *(const float4*)(Wp + 4);
    {
        float tmp[8] = {a0.x, a0.y, a0.z, a0.w, a1.x, a1.y, a1.z, a1.w};
#pragma unroll
        for (int j = 0; j < 8; j++) As[0][ak + j][arow] = tmp[j];
        *(float4*)&Ws[0][wrow][wcol] = w0;
        *(float4*)&Ws[0][wrow][wcol + 4] = w1;
    }
    __syncthreads();

    for (int kt = 0; kt < nk; kt++) {
        int cur = kt & 1;
        if (kt + 1 < nk) {
            const float* An = Ap + (kt + 1) * 16;
            const float* Wn = Wp + (size_t)(kt + 1) * 16 * N;
            a0 = *(const float4*)(An);
            a1 = *(const float4*)(An + 4);
            w0 = *(const float4*)(Wn);
            w1 = *(const float4*)(Wn + 4);
        }
#pragma unroll
        for (int kk = 0; kk < 16; kk++) {
            float av[8], bv[8];
            *(float4*)&av[0] = *(const float4*)&As[cur][kk][ty * 8];
            *(float4*)&av[4] = *(const float4*)&As[cur][kk][ty * 8 + 4];
            *(float4*)&bv[0] = *(const float4*)&Ws[cur][kk][tx * 8];
            *(float4*)&bv[4] = *(const float4*)&Ws[cur][kk][tx * 8 + 4];
#pragma unroll
            for (int i = 0; i < 8; i++)
#pragma unroll
                for (int j = 0; j < 8; j++)
                    acc[i][j] += av[i] * bv[j];
        }
        if (kt + 1 < nk) {
            int nxt = cur ^ 1;
            float tmp[8] = {a0.x, a0.y, a0.z, a0.w, a1.x, a1.y, a1.z, a1.w};
#pragma unroll
            for (int j = 0; j < 8; j++) As[nxt][ak + j][arow] = tmp[j];
            *(float4*)&Ws[nxt][wrow][wcol] = w0;
            *(float4*)&Ws[nxt][wrow][wcol + 4] = w1;
        }
        __syncthreads();
    }

    float* out = part + (size_t)p * 2048 * 512;
#pragma unroll
    for (int i = 0; i < 8; i++) {
        float* cp = out + (size_t)(m0 + ty * 8 + i) * N + n0 + tx * 8;
        *(float4*)cp = *(float4*)&acc[i][0];
        *(float4*)(cp + 4) = *(float4*)&acc[i][4];
    }
}

// ---------------------------------------------------------------------------
// Sum conv partials + bias, then LayerNorm. One block (256 thr) per row.
// ---------------------------------------------------------------------------
__global__ void ln_fuse_kernel(const float* __restrict__ part,
                               const float* __restrict__ bsr,
                               const float* __restrict__ gamma,
                               const float* __restrict__ beta,
                               float* __restrict__ xs) {
    __shared__ float red[256];
    __shared__ float s_mean, s_inv;
    const size_t RS = (size_t)2048 * 512;
    int t = threadIdx.x;
    size_t ro = (size_t)blockIdx.x * 512;

    float v0 = part[ro + t] + part[RS + ro + t] + part[2 * RS + ro + t] +
               part[3 * RS + ro + t] + bsr[t];
    int t2 = t + 256;
    float v1 = part[ro + t2] + part[RS + ro + t2] + part[2 * RS + ro + t2] +
               part[3 * RS + ro + t2] + bsr[t2];

    red[t] = v0 + v1;
    __syncthreads();
    for (int off = 128; off; off >>= 1) {
        if (t < off) red[t] += red[t + off];
        __syncthreads();
    }
    if (t == 0) s_mean = red[0] * (1.f / 512.f);
    __syncthreads();
    float mean = s_mean;
    float d0 = v0 - mean, d1 = v1 - mean;
    red[t] = d0 * d0 + d1 * d1;
    __syncthreads();
    for (int off = 128; off; off >>= 1) {
        if (t < off) red[t] += red[t + off];
        __syncthreads();
    }
    if (t == 0) s_inv = rsqrtf(red[0] * (1.f / 512.f) + LN_EPS);
    __syncthreads();
    float inv = s_inv;
    xs[ro + t]  = d0 * inv * gamma[t]  + beta[t];
    xs[ro + t2] = d1 * inv * gamma[t2] + beta[t2];
}

// ---------------------------------------------------------------------------
// Transpose K half of kv into kT[b*8+h][d][token] (d-major) so attention
// K-tile smem loads are conflict-free float4s.
// ---------------------------------------------------------------------------
__global__ void transpose_k_kernel(const float* __restrict__ kv,
                                   float* __restrict__ kT) {
    __shared__ float sm[64 * 65];
    int bh = blockIdx.y;
    int b = bh >> 3, h = bh & 7;
    int t0 = blockIdx.x * 64;
    int tid = threadIdx.x;

    const float* src = kv + (size_t)b * 1024 * 1024 + h * 64;
#pragma unroll
    for (int l = 0; l < 4; l++) {
        int f4 = tid + l * 256;
        int n = f4 >> 4, d4 = f4 & 15;
        float4 v = *(const float4*)(src + (size_t)(t0 + n) * 1024 + d4 * 4);
        sm[(d4 * 4 + 0) * 65 + n] = v.x;
        sm[(d4 * 4 + 1) * 65 + n] = v.y;
        sm[(d4 * 4 + 2) * 65 + n] = v.z;
        sm[(d4 * 4 + 3) * 65 + n] = v.w;
    }
    __syncthreads();
    float* dst = kT + (size_t)bh * 64 * 1024;
#pragma unroll
    for (int l = 0; l < 4; l++) {
        int f4 = tid + l * 256;
        int d = f4 >> 4, n4 = f4 & 15;
        float4 v;
        v.x = sm[d * 65 + n4 * 4 + 0];
        v.y = sm[d * 65 + n4 * 4 + 1];
        v.z = sm[d * 65 + n4 * 4 + 2];
        v.w = sm[d * 65 + n4 * 4 + 3];
        *(float4*)(dst + (size_t)d * 1024 + t0 + n4 * 4) = v;
    }
}

// ---------------------------------------------------------------------------
// Flash attention v2: 128 q-rows per block, 128 threads, 8x8 micro for both
// QK^T and P@V (1 B/FMA). Online softmax, one thread per row.
// smem: Qs[64][132] (d,m) | Ks[64][68] (d,n) | Vs[64][68] (n,d) | Pt[64][132] (n,m)
// ---------------------------------------------------------------------------
#define AT_QP 132
#define AT_KP 68
#define ATTN_SMEM_FLOATS (64 * AT_QP + 64 * AT_KP + 64 * AT_KP + 64 * AT_QP + 3 * 128)

__global__ __launch_bounds__(128, 2)
void attn2_kernel(const float* __restrict__ q,
                  const float* __restrict__ kv,
                  const float* __restrict__ kT,
                  float* __restrict__ ao) {
    extern __shared__ __align__(16) float sm[];
    float* Qs = sm;                     // 64 x 132  [d][m]
    float* Ks = Qs + 64 * AT_QP;        // 64 x 68   [d][n]
    float* Vs = Ks + 64 * AT_KP;        // 64 x 68   [n][d]
    float* Pt = Vs + 64 * AT_KP;        // 64 x 132  [n][m]
    float* m_s = Pt + 64 * AT_QP;       // 128
    float* l_s = m_s + 128;
    float* cf  = l_s + 128;

    int tid = threadIdx.x;
    int tx = tid & 7, ty = tid >> 3;    // rows m: ty*8.., cols: tx*8..
    int b = blockIdx.z, h = blockIdx.y;
    int q0 = blockIdx.x * 128;

    // load Q transposed (one-time)
    const float* qb = q + ((size_t)(b * 4096 + q0)) * 512 + h * 64;
#pragma unroll
    for (int l = 0; l < 16; l++) {
        int f4 = tid + l * 128;
        int r = f4 >> 4, c4 = f4 & 15;
        float4 v = *(const float4*)(qb + (size_t)r * 512 + c4 * 4);
        Qs[(c4 * 4 + 0) * AT_QP + r] = v.x;
        Qs[(c4 * 4 + 1) * AT_QP + r] = v.y;
        Qs[(c4 * 4 + 2) * AT_QP + r] = v.z;
        Qs[(c4 * 4 + 3) * AT_QP + r] = v.w;
    }
    m_s[tid] = -3.0e38f;
    l_s[tid] = 0.f;
    float o[8][8] = {};
    __syncthreads();

    const float* kTb = kT + (size_t)(b * 8 + h) * 64 * 1024;
    const float* vb = kv + (size_t)b * 1024 * 1024 + 512 + h * 64;

    for (int t = 0; t < 16; t++) {
        // load K [d][n] (from kT, conflict-free) and V [n][d]
#pragma unroll
        for (int l = 0; l < 8; l++) {
            int f4 = tid + l * 128;
            int r = f4 >> 4, c4 = f4 & 15;
            *(float4*)&Ks[r * AT_KP + c4 * 4] =
                *(const float4*)(kTb + (size_t)r * 1024 + t * 64 + c4 * 4);
            *(float4*)&Vs[r * AT_KP + c4 * 4] =
                *(const float4*)(vb + (size_t)(t * 64 + r) * 1024 + c4 * 4);
        }
        __syncthreads();

        // S = Q K^T  (8x8 micro)
        float s[8][8] = {};
#pragma unroll 8
        for (int d = 0; d < 64; d++) {
            float av[8], bv[8];
            *(float4*)&av[0] = *(const float4*)&Qs[d * AT_QP + ty * 8];
            *(float4*)&av[4] = *(const float4*)&Qs[d * AT_QP + ty * 8 + 4];
            *(float4*)&bv[0] = *(const float4*)&Ks[d * AT_KP + tx * 8];
            *(float4*)&bv[4] = *(const float4*)&Ks[d * AT_KP + tx * 8 + 4];
#pragma unroll
            for (int i = 0; i < 8; i++)
#pragma unroll
                for (int j = 0; j < 8; j++)
                    s[i][j] += av[i] * bv[j];
        }
        // store S^T scaled into Pt[n][m]
#pragma unroll
        for (int j = 0; j < 8; j++) {
            float4 u0, u1;
            u0.x = s[0][j] * 0.125f; u0.y = s[1][j] * 0.125f;
            u0.z = s[2][j] * 0.125f; u0.w = s[3][j] * 0.125f;
            u1.x = s[4][j] * 0.125f; u1.y = s[5][j] * 0.125f;
            u1.z = s[6][j] * 0.125f; u1.w = s[7][j] * 0.125f;
            *(float4*)&Pt[(tx * 8 + j) * AT_QP + ty * 8] = u0;
            *(float4*)&Pt[(tx * 8 + j) * AT_QP + ty * 8 + 4] = u1;
        }
        __syncthreads();

        // online softmax: one thread per q-row
        {
            float mo = m_s[tid];
            float mx = mo;
#pragma unroll 16
            for (int c = 0; c < 64; c++) mx = fmaxf(mx, Pt[c * AT_QP + tid]);
            float corr = exp2f((mo - mx) * LOG2E);
            float ls = 0.f;
#pragma unroll 8
            for (int c = 0; c < 64; c++) {
                float e = exp2f((Pt[c * AT_QP + tid] - mx) * LOG2E);
                Pt[c * AT_QP + tid] = e;
                ls += e;
            }
            l_s[tid] = l_s[tid] * corr + ls;
            m_s[tid] = mx;
            cf[tid] = corr;
        }
        __syncthreads();

        // rescale O, accumulate O += P @ V  (8x8 micro over n)
        float cr[8];
#pragma unroll
        for (int i = 0; i < 8; i++) cr[i] = cf[ty * 8 + i];
#pragma unroll
        for (int i = 0; i < 8; i++)
#pragma unroll
            for (int j = 0; j < 8; j++) o[i][j] *= cr[i];

#pragma unroll 8
        for (int n = 0; n < 64; n++) {
            float pv[8], vv[8];
            *(float4*)&pv[0] = *(const float4*)&Pt[n * AT_QP + ty * 8];
            *(float4*)&pv[4] = *(const float4*)&Pt[n * AT_QP + ty * 8 + 4];
            *(float4*)&vv[0] = *(const float4*)&Vs[n * AT_KP + tx * 8];
            *(float4*)&vv[4] = *(const float4*)&Vs[n * AT_KP + tx * 8 + 4];
#pragma unroll
            for (int i = 0; i < 8; i++)
#pragma unroll
                for (int j = 0; j < 8; j++)
                    o[i][j] += pv[i] * vv[j];
        }
        __syncthreads();
    }

    // epilogue
    float* ob = ao + ((size_t)(b * 4096 + q0)) * 512 + h * 64;
#pragma unroll
    for (int i = 0; i < 8; i++) {
        float inv = 1.f / l_s[ty * 8 + i];
        float4 r0, r1;
        r0.x = o[i][0] * inv; r0.y = o[i][1] * inv;
        r0.z = o[i][2] * inv; r0.w = o[i][3] * inv;
        r1.x = o[i][4] * inv; r1.y = o[i][5] * inv;
        r1.z = o[i][6] * inv; r1.w = o[i][7] * inv;
        float* cp = ob + (size_t)(ty * 8 + i) * 512 + tx * 8;
        *(float4*)cp = r0;
        *(float4*)(cp + 4) = r1;
    }
}

// ---------------------------------------------------------------------------
// Launch
// ---------------------------------------------------------------------------
extern "C" void kernel_launch(void* const* d_in, const int* in_sizes, int n_in,
                              void* d_out, int out_size) {
    (void)in_sizes; (void)n_in; (void)out_size;

    const float* x     = (const float*)d_in[0];
    const float* Wq    = (const float*)d_in[1];
    const float* bq    = (const float*)d_in[2];
    const float* Wkv   = (const float*)d_in[3];
    const float* bkv   = (const float*)d_in[4];
    const float* Wproj = (const float*)d_in[5];
    const float* bproj = (const float*)d_in[6];
    const float* Aq    = (const float*)d_in[7];
    const float* Bq    = (const float*)d_in[8];
    const float* Av    = (const float*)d_in[9];
    const float* Bv    = (const float*)d_in[10];
    const float* Wsr   = (const float*)d_in[11];
    const float* bsr   = (const float*)d_in[12];
    const float* gamma = (const float*)d_in[13];
    const float* beta  = (const float*)d_in[14];
    float* out = (float*)d_out;

    float *WqE, *WkvE, *qbuf, *xs, *kvbuf, *kT, *convp, *ao;
    cudaGetSymbolAddress((void**)&WqE,   g_WqE);
    cudaGetSymbolAddress((void**)&WkvE,  g_WkvE);
    cudaGetSymbolAddress((void**)&qbuf,  g_q);
    cudaGetSymbolAddress((void**)&xs,    g_xs);
    cudaGetSymbolAddress((void**)&kvbuf, g_kv);
    cudaGetSymbolAddress((void**)&kT,    g_kT);
    cudaGetSymbolAddress((void**)&convp, g_convp);
    cudaGetSymbolAddress((void**)&ao,    g_ao);

    // 1) fold LoRA into weights
    prep_wq_kernel<<<1024, 256>>>(Wq, Aq, Bq, WqE);
    prep_wkv_kernel<<<2048, 256>>>(Wkv, Av, Bv, WkvE);

    // 2) q = x @ WqE + bq           (M=8192, N=512)
    sgemm128_kernel<<<dim3(64, 4), 256>>>(x, WqE, bq, qbuf, 8192, 512, 512);

    // 3) conv as 4 split-K GEMMs    (M=2048, N=512, K=512 each)
    conv_gemm_kernel<<<dim3(16, 4, 4), 256>>>(x, Wsr, convp);

    // 4) sum partials + bias + LayerNorm
    ln_fuse_kernel<<<2048, 256>>>(convp, bsr, gamma, beta, xs);

    // 5) kv = xs @ WkvE + bkv       (M=2048, N=1024)
    sgemm128_kernel<<<dim3(16, 8), 256>>>(xs, WkvE, bkv, kvbuf, 2048, 1024, 512);

    // 6) transpose K for attention
    transpose_k_kernel<<<dim3(16, 16), 256>>>(kvbuf, kT);

    // 7) fused flash attention      (32 q-tiles x 8 heads x 2 batch)
    size_t attn_smem = ATTN_SMEM_FLOATS * sizeof(float);
    cudaFuncSetAttribute(attn2_kernel, cudaFuncAttributeMaxDynamicSharedMemorySize,
                         (int)attn_smem);
    attn2_kernel<<<dim3(32, 8, 2), 128, attn_smem>>>(qbuf, kvbuf, kT, ao);

    // 8) out = ao @ Wproj + bproj   (M=8192, N=512)
    sgemm128_kernel<<<dim3(64, 4), 256>>>(ao, Wproj, bproj, out, 8192, 512, 512);
}

// round 5
// speedup vs baseline: 2.1838x; 1.9090x over previous
#include <cuda_runtime.h>
#include <cuda_bf16.h>
#include <math.h>
#include <stddef.h>
#include <stdint.h>

#define LN_EPS 1e-5f
#define LOG2E 1.44269504088896340736f
typedef __nv_bfloat16 bf16;

// ===========================================================================
// mma.sync / ldmatrix / cp.async primitives (compute_100 baseline PTX)
// ===========================================================================
__device__ __forceinline__ uint32_t smem_u32(const void* p) {
    uint32_t a;
    asm("{ .reg .u64 t; cvta.to.shared.u64 t, %1; cvt.u32.u64 %0, t; }"
        : "=r"(a) : "l"(p));
    return a;
}

__device__ __forceinline__ void mma_bf16(float* d, const uint32_t* a,
                                         uint32_t b0, uint32_t b1) {
    asm volatile(
        "mma.sync.aligned.m16n8k16.row.col.f32.bf16.bf16.f32 "
        "{%0,%1,%2,%3}, {%4,%5,%6,%7}, {%8,%9}, {%0,%1,%2,%3};"
        : "+f"(d[0]), "+f"(d[1]), "+f"(d[2]), "+f"(d[3])
        : "r"(a[0]), "r"(a[1]), "r"(a[2]), "r"(a[3]), "r"(b0), "r"(b1));
}

__device__ __forceinline__ void ldmat4(uint32_t* r, uint32_t addr) {
    asm volatile("ldmatrix.sync.aligned.m8n8.x4.shared.b16 {%0,%1,%2,%3}, [%4];"
        : "=r"(r[0]), "=r"(r[1]), "=r"(r[2]), "=r"(r[3]) : "r"(addr));
}
__device__ __forceinline__ void ldmat4t(uint32_t* r, uint32_t addr) {
    asm volatile("ldmatrix.sync.aligned.m8n8.x4.trans.shared.b16 {%0,%1,%2,%3}, [%4];"
        : "=r"(r[0]), "=r"(r[1]), "=r"(r[2]), "=r"(r[3]) : "r"(addr));
}

__device__ __forceinline__ void cp16(uint32_t s, const void* g) {
    asm volatile("cp.async.cg.shared.global [%0], [%1], 16;" :: "r"(s), "l"(g));
}
#define CP_COMMIT() asm volatile("cp.async.commit_group;")
#define CP_WAIT(N)  asm volatile("cp.async.wait_group %0;" :: "n"(N))

__device__ __forceinline__ uint32_t pack_bf2(bf16 a, bf16 b) {
    __nv_bfloat162 t(a, b);
    return *reinterpret_cast<uint32_t*>(&t);
}
__device__ __forceinline__ void split2(float v, bf16& h, bf16& l) {
    h = __float2bfloat16(v);
    l = __float2bfloat16(v - __bfloat162float(h));
}

// ===========================================================================
// Scratch
// ===========================================================================
__device__ float g_q[2 * 4096 * 512];
__device__ float g_xs[2 * 1024 * 512];
__device__ float g_kv[2 * 1024 * 1024];
__device__ float g_ao[2 * 4096 * 512];

__device__ bf16 g_xhi[4194304],  g_xlo[4194304];
__device__ bf16 g_xshi[1048576], g_xslo[1048576];
__device__ bf16 g_aohi[4194304], g_aolo[4194304];
__device__ bf16 g_qhi[4194304],  g_qlo[4194304];          // q * 0.125, split
__device__ bf16 g_khi[1048576],  g_klo[1048576];
__device__ bf16 g_vhi[1048576],  g_vlo[1048576];
__device__ bf16 g_WqTh[262144],  g_WqTl[262144];          // [n][k]
__device__ bf16 g_WkvTh[524288], g_WkvTl[524288];
__device__ bf16 g_WpTh[262144],  g_WpTl[262144];
__device__ bf16 g_WsrTh[1048576], g_WsrTl[1048576];       // [p][n][k]

// ===========================================================================
// Weight prep: fold LoRA, transpose to [n][k], split hi/lo
// ===========================================================================
__global__ void prep_wqT_kernel(const float* __restrict__ Wq,
                                const float* __restrict__ Aq,
                                const float* __restrict__ Bq,
                                bf16* __restrict__ Th, bf16* __restrict__ Tl) {
    int idx = blockIdx.x * blockDim.x + threadIdx.x;
    int n = idx >> 9, k = idx & 511;
    float w = Wq[k * 512 + n];
#pragma unroll
    for (int r = 0; r < 8; r++) w += Aq[k * 8 + r] * Bq[r * 512 + n];
    split2(w, Th[idx], Tl[idx]);
}

__global__ void prep_wkvT_kernel(const float* __restrict__ Wkv,
                                 const float* __restrict__ Av,
                                 const float* __restrict__ Bv,
                                 bf16* __restrict__ Th, bf16* __restrict__ Tl) {
    int idx = blockIdx.x * blockDim.x + threadIdx.x;   // idx = n*512+k, n<1024
    int n = idx >> 9, k = idx & 511, ln = n & 511;
    float w = Wkv[k * 1024 + n];
#pragma unroll
    for (int r = 0; r < 8; r++) w += Av[k * 8 + r] * Bv[r * 512 + ln];
    split2(w, Th[idx], Tl[idx]);
}

__global__ void prep_wpT_kernel(const float* __restrict__ Wp,
                                bf16* __restrict__ Th, bf16* __restrict__ Tl) {
    int idx = blockIdx.x * blockDim.x + threadIdx.x;
    int n = idx >> 9, k = idx & 511;
    split2(Wp[k * 512 + n], Th[idx], Tl[idx]);
}

__global__ void prep_wsrT_kernel(const float* __restrict__ Wsr,
                                 bf16* __restrict__ Th, bf16* __restrict__ Tl) {
    int idx = blockIdx.x * blockDim.x + threadIdx.x;   // (p*512+n)*512+k
    int p = idx >> 18, rem = idx & 262143;
    int n = rem >> 9, k = rem & 511;
    split2(Wsr[(size_t)p * 262144 + k * 512 + n], Th[idx], Tl[idx]);
}

// ===========================================================================
// Activation splits
// ===========================================================================
__global__ void split_kernel(const float* __restrict__ src,
                             bf16* __restrict__ hi, bf16* __restrict__ lo) {
    int i = blockIdx.x * blockDim.x + threadIdx.x;
    float4 v = ((const float4*)src)[i];
    bf16 h0, h1, h2, h3, l0, l1, l2, l3;
    split2(v.x, h0, l0); split2(v.y, h1, l1);
    split2(v.z, h2, l2); split2(v.w, h3, l3);
    __nv_bfloat162* hp = (__nv_bfloat162*)hi;
    __nv_bfloat162* lp = (__nv_bfloat162*)lo;
    hp[i * 2] = __nv_bfloat162(h0, h1); hp[i * 2 + 1] = __nv_bfloat162(h2, h3);
    lp[i * 2] = __nv_bfloat162(l0, l1); lp[i * 2 + 1] = __nv_bfloat162(l2, l3);
}

__global__ void split_scale_kernel(const float* __restrict__ src,
                                   bf16* __restrict__ hi, bf16* __restrict__ lo) {
    int i = blockIdx.x * blockDim.x + threadIdx.x;
    float4 v = ((const float4*)src)[i];
    v.x *= 0.125f; v.y *= 0.125f; v.z *= 0.125f; v.w *= 0.125f;
    bf16 h0, h1, h2, h3, l0, l1, l2, l3;
    split2(v.x, h0, l0); split2(v.y, h1, l1);
    split2(v.z, h2, l2); split2(v.w, h3, l3);
    __nv_bfloat162* hp = (__nv_bfloat162*)hi;
    __nv_bfloat162* lp = (__nv_bfloat162*)lo;
    hp[i * 2] = __nv_bfloat162(h0, h1); hp[i * 2 + 1] = __nv_bfloat162(h2, h3);
    lp[i * 2] = __nv_bfloat162(l0, l1); lp[i * 2 + 1] = __nv_bfloat162(l2, l3);
}

// kv [row][1024] -> k hi/lo, v hi/lo [row][512]
__global__ void split_kv_kernel(const float* __restrict__ kv,
                                bf16* __restrict__ kh, bf16* __restrict__ kl,
                                bf16* __restrict__ vh, bf16* __restrict__ vl) {
    int i = blockIdx.x * blockDim.x + threadIdx.x;   // 2048 rows * 128 float4
    int row = i >> 7, c4 = i & 127;
    const float* base = kv + (size_t)row * 1024;
    float4 kvv = ((const float4*)base)[c4];
    float4 vvv = ((const float4*)(base + 512))[c4];
    bf16 h0, h1, h2, h3, l0, l1, l2, l3;
    split2(kvv.x, h0, l0); split2(kvv.y, h1, l1);
    split2(kvv.z, h2, l2); split2(kvv.w, h3, l3);
    size_t o = (size_t)row * 512 + c4 * 4;
    ((__nv_bfloat162*)(kh + o))[0] = __nv_bfloat162(h0, h1);
    ((__nv_bfloat162*)(kh + o))[1] = __nv_bfloat162(h2, h3);
    ((__nv_bfloat162*)(kl + o))[0] = __nv_bfloat162(l0, l1);
    ((__nv_bfloat162*)(kl + o))[1] = __nv_bfloat162(l2, l3);
    split2(vvv.x, h0, l0); split2(vvv.y, h1, l1);
    split2(vvv.z, h2, l2); split2(vvv.w, h3, l3);
    ((__nv_bfloat162*)(vh + o))[0] = __nv_bfloat162(h0, h1);
    ((__nv_bfloat162*)(vh + o))[1] = __nv_bfloat162(h2, h3);
    ((__nv_bfloat162*)(vl + o))[0] = __nv_bfloat162(l0, l1);
    ((__nv_bfloat162*)(vl + o))[1] = __nv_bfloat162(l2, l3);
}

// ===========================================================================
// mma.sync GEMM, bf16x3: C[M,N] = A @ B^T + bias
// A hi/lo [M][K]; B hi/lo [N][K]. Block tile 128x128, Kchunk 32, 8 warps.
// CONV: A rows gathered from x, B = [p][512][512], K = 2048.
// ===========================================================================
#define G_STAGE 40960   // 4 tiles x 128 rows x 40 bf16 (80 B)
#define G_TA_HI 0
#define G_TA_LO 10240
#define G_TB_HI 20480
#define G_TB_LO 30720
#define G_SMEM  (2 * G_STAGE)

template <bool CONV>
__global__ __launch_bounds__(256)
void gemm_mma(const bf16* __restrict__ Ah, const bf16* __restrict__ Al,
              const bf16* __restrict__ Bh, const bf16* __restrict__ Bl,
              const float* __restrict__ bias, float* __restrict__ C,
              int M, int N, int K) {
    extern __shared__ __align__(16) char smem[];
    uint32_t sb = smem_u32(smem);
    int tid = threadIdx.x, lane = tid & 31, w = tid >> 5;
    int wm = w & 3, wn = w >> 2;
    int m0 = blockIdx.x * 128, n0 = blockIdx.y * 128;
    int nch = K >> 5;

    float acc[2][8][4] = {};

    // ---- loader ----
    auto issue = [&](int c) {
        uint32_t sbase = sb + (c & 1) * G_STAGE;
#pragma unroll
        for (int i = 0; i < 2; i++) {
            int idx = tid + i * 256;          // 512 chunks
            int r = idx >> 2, g = idx & 3;
            uint32_t dst = (uint32_t)(r * 80 + g * 16);
            size_t aoff, boff;
            if (CONV) {
                int p = c >> 4;
                int koff = (c & 15) * 32 + g * 8;
                int m = m0 + r;
                int bb = m >> 10, s = m & 1023;
                int oh = s >> 5, ow = s & 31;
                int xr = (2 * oh + (p >> 1)) * 64 + 2 * ow + (p & 1);
                aoff = ((size_t)(bb * 4096 + xr)) * 512 + koff;
                boff = ((size_t)(p * 512 + n0 + r)) * 512 + koff;
            } else {
                aoff = (size_t)(m0 + r) * K + c * 32 + g * 8;
                boff = (size_t)(n0 + r) * K + c * 32 + g * 8;
            }
            cp16(sbase + G_TA_HI + dst, Ah + aoff);
            cp16(sbase + G_TA_LO + dst, Al + aoff);
            cp16(sbase + G_TB_HI + dst, Bh + boff);
            cp16(sbase + G_TB_LO + dst, Bl + boff);
        }
    };

    // per-thread ldmatrix bases
    uint32_t aoffs = (uint32_t)((wm * 32 + (lane & 15)) * 80 + (lane >> 4) * 16);
    uint32_t boffs = (uint32_t)((wn * 64 + ((lane >> 4) & 1) * 8 + (lane & 7)) * 80
                                + ((lane >> 3) & 1) * 16);

    issue(0); CP_COMMIT();

    for (int c = 0; c < nch; c++) {
        if (c + 1 < nch) { issue(c + 1); CP_COMMIT(); CP_WAIT(1); }
        else             { CP_WAIT(0); }
        __syncthreads();

        uint32_t sbase = sb + (c & 1) * G_STAGE;
#pragma unroll
        for (int ks = 0; ks < 2; ks++) {
            uint32_t ah[2][4], al[2][4];
#pragma unroll
            for (int mi = 0; mi < 2; mi++) {
                ldmat4(ah[mi], sbase + G_TA_HI + aoffs + mi * 1280 + ks * 32);
                ldmat4(al[mi], sbase + G_TA_LO + aoffs + mi * 1280 + ks * 32);
            }
#pragma unroll
            for (int jj = 0; jj < 4; jj++) {
                uint32_t bh4[4], bl4[4];
                ldmat4(bh4, sbase + G_TB_HI + boffs + jj * 1280 + ks * 32);
                ldmat4(bl4, sbase + G_TB_LO + boffs + jj * 1280 + ks * 32);
#pragma unroll
                for (int mi = 0; mi < 2; mi++) {
                    mma_bf16(acc[mi][2 * jj],     ah[mi], bh4[0], bh4[1]);
                    mma_bf16(acc[mi][2 * jj],     ah[mi], bl4[0], bl4[1]);
                    mma_bf16(acc[mi][2 * jj],     al[mi], bh4[0], bh4[1]);
                    mma_bf16(acc[mi][2 * jj + 1], ah[mi], bh4[2], bh4[3]);
                    mma_bf16(acc[mi][2 * jj + 1], ah[mi], bl4[2], bl4[3]);
                    mma_bf16(acc[mi][2 * jj + 1], al[mi], bh4[2], bh4[3]);
                }
            }
        }
        __syncthreads();
    }

    // ---- epilogue ----
#pragma unroll
    for (int mi = 0; mi < 2; mi++) {
        int row = m0 + wm * 32 + mi * 16 + (lane >> 2);
#pragma unroll
        for (int nj = 0; nj < 8; nj++) {
            int col = n0 + wn * 64 + nj * 8 + (lane & 3) * 2;
            float b0 = bias[col], b1 = bias[col + 1];
            float2 v0 = {acc[mi][nj][0] + b0, acc[mi][nj][1] + b1};
            float2 v1 = {acc[mi][nj][2] + b0, acc[mi][nj][3] + b1};
            *(float2*)&C[(size_t)row * N + col] = v0;
            *(float2*)&C[(size_t)(row + 8) * N + col] = v1;
        }
    }
}

// ===========================================================================
// LayerNorm over C=512 in place
// ===========================================================================
__global__ void ln_kernel(float* __restrict__ xs,
                          const float* __restrict__ gamma,
                          const float* __restrict__ beta) {
    __shared__ float red[256];
    __shared__ float s_mean, s_inv;
    int t = threadIdx.x;
    float* p = xs + (size_t)blockIdx.x * 512;
    float v0 = p[t], v1 = p[t + 256];
    red[t] = v0 + v1;
    __syncthreads();
    for (int off = 128; off; off >>= 1) {
        if (t < off) red[t] += red[t + off];
        __syncthreads();
    }
    if (t == 0) s_mean = red[0] * (1.f / 512.f);
    __syncthreads();
    float mean = s_mean;
    float d0 = v0 - mean, d1 = v1 - mean;
    red[t] = d0 * d0 + d1 * d1;
    __syncthreads();
    for (int off = 128; off; off >>= 1) {
        if (t < off) red[t] += red[t + off];
        __syncthreads();
    }
    if (t == 0) s_inv = rsqrtf(red[0] * (1.f / 512.f) + LN_EPS);
    __syncthreads();
    float inv = s_inv;
    p[t]       = d0 * inv * gamma[t]       + beta[t];
    p[t + 256] = d1 * inv * gamma[t + 256] + beta[t + 256];
}

// ===========================================================================
// Flash attention, mma.sync, bf16x3 for QK^T and PV.
// Block: 128 q rows x (b,h); 8 warps, warp = 16 q rows. kv = 16 tiles of 64.
// smem (bf16, stride 72 elems = 144 B):
//   QH/QL [128][72], KH/KL [64][72], VH/VL [64][72]
// ===========================================================================
#define A_QH 0
#define A_QL 18432
#define A_KH 36864
#define A_KL 46080
#define A_VH 55296
#define A_VL 64512
#define A_SMEM 73728

__global__ __launch_bounds__(256)
void attn_mma(const bf16* __restrict__ qh, const bf16* __restrict__ ql,
              const bf16* __restrict__ kh, const bf16* __restrict__ kl,
              const bf16* __restrict__ vh, const bf16* __restrict__ vl,
              float* __restrict__ ao) {
    extern __shared__ __align__(16) char smem[];
    uint32_t sb = smem_u32(smem);
    int tid = threadIdx.x, lane = tid & 31, w = tid >> 5;
    int b = blockIdx.z, h = blockIdx.y;
    int q0 = blockIdx.x * 128;

    // ---- load Q tile ----
    size_t qbase = ((size_t)(b * 4096 + q0)) * 512 + h * 64;
#pragma unroll
    for (int i = 0; i < 4; i++) {
        int idx = tid + i * 256;            // 1024 chunks
        int r = idx >> 3, g = idx & 7;
        uint32_t dst = (uint32_t)(r * 144 + g * 16);
        size_t src = qbase + (size_t)r * 512 + g * 8;
        *(uint4*)(smem + A_QH + dst) = *(const uint4*)(qh + src);
        *(uint4*)(smem + A_QL + dst) = *(const uint4*)(ql + src);
    }
    __syncthreads();

    // ---- hoist Q fragments ----
    uint32_t qf_h[4][4], qf_l[4][4];
    uint32_t qoffs = (uint32_t)((w * 16 + (lane & 15)) * 144 + (lane >> 4) * 16);
#pragma unroll
    for (int ks = 0; ks < 4; ks++) {
        ldmat4(qf_h[ks], sb + A_QH + qoffs + ks * 32);
        ldmat4(qf_l[ks], sb + A_QL + qoffs + ks * 32);
    }

    float o[8][4] = {};
    float mrun0 = -3.0e38f, mrun1 = -3.0e38f, lrun0 = 0.f, lrun1 = 0.f;
    size_t kvbase = ((size_t)b * 1024) * 512 + h * 64;

    uint32_t koffs = (uint32_t)((((lane >> 4) & 1) * 8 + (lane & 7)) * 144
                                + ((lane >> 3) & 1) * 16);
    uint32_t voffs = (uint32_t)((((lane >> 3) & 1) * 8 + (lane & 7)) * 144
                                + (lane >> 4) * 16);

    for (int t = 0; t < 16; t++) {
        __syncthreads();
#pragma unroll
        for (int i = 0; i < 2; i++) {
            int idx = tid + i * 256;        // 512 chunks
            int r = idx >> 3, g = idx & 7;
            uint32_t dst = (uint32_t)(r * 144 + g * 16);
            size_t src = kvbase + (size_t)(t * 64 + r) * 512 + g * 8;
            *(uint4*)(smem + A_KH + dst) = *(const uint4*)(kh + src);
            *(uint4*)(smem + A_KL + dst) = *(const uint4*)(kl + src);
            *(uint4*)(smem + A_VH + dst) = *(const uint4*)(vh + src);
            *(uint4*)(smem + A_VL + dst) = *(const uint4*)(vl + src);
        }
        __syncthreads();

        // ---- S = Q K^T ----
        float s[8][4] = {};
#pragma unroll
        for (int ks = 0; ks < 4; ks++) {
#pragma unroll
            for (int jj = 0; jj < 4; jj++) {
                uint32_t bh4[4], bl4[4];
                ldmat4(bh4, sb + A_KH + koffs + jj * 2304 + ks * 32);
                ldmat4(bl4, sb + A_KL + koffs + jj * 2304 + ks * 32);
                mma_bf16(s[2 * jj],     qf_h[ks], bh4[0], bh4[1]);
                mma_bf16(s[2 * jj],     qf_h[ks], bl4[0], bl4[1]);
                mma_bf16(s[2 * jj],     qf_l[ks], bh4[0], bh4[1]);
                mma_bf16(s[2 * jj + 1], qf_h[ks], bh4[2], bh4[3]);
                mma_bf16(s[2 * jj + 1], qf_h[ks], bl4[2], bl4[3]);
                mma_bf16(s[2 * jj + 1], qf_l[ks], bh4[2], bh4[3]);
            }
        }

        // ---- online softmax (rows: r0 = lane>>2, r1 = r0+8) ----
        float tm0 = -3.0e38f, tm1 = -3.0e38f;
#pragma unroll
        for (int nj = 0; nj < 8; nj++) {
            tm0 = fmaxf(tm0, fmaxf(s[nj][0], s[nj][1]));
            tm1 = fmaxf(tm1, fmaxf(s[nj][2], s[nj][3]));
        }
        tm0 = fmaxf(tm0, __shfl_xor_sync(0xffffffffu, tm0, 1));
        tm0 = fmaxf(tm0, __shfl_xor_sync(0xffffffffu, tm0, 2));
        tm1 = fmaxf(tm1, __shfl_xor_sync(0xffffffffu, tm1, 1));
        tm1 = fmaxf(tm1, __shfl_xor_sync(0xffffffffu, tm1, 2));
        float mn0 = fmaxf(mrun0, tm0), mn1 = fmaxf(mrun1, tm1);
        float corr0 = exp2f((mrun0 - mn0) * LOG2E);
        float corr1 = exp2f((mrun1 - mn1) * LOG2E);
        mrun0 = mn0; mrun1 = mn1;
        float ls0 = 0.f, ls1 = 0.f;
#pragma unroll
        for (int nj = 0; nj < 8; nj++) {
            s[nj][0] = exp2f((s[nj][0] - mn0) * LOG2E);
            s[nj][1] = exp2f((s[nj][1] - mn0) * LOG2E);
            s[nj][2] = exp2f((s[nj][2] - mn1) * LOG2E);
            s[nj][3] = exp2f((s[nj][3] - mn1) * LOG2E);
            ls0 += s[nj][0] + s[nj][1];
            ls1 += s[nj][2] + s[nj][3];
        }
        ls0 += __shfl_xor_sync(0xffffffffu, ls0, 1);
        ls0 += __shfl_xor_sync(0xffffffffu, ls0, 2);
        ls1 += __shfl_xor_sync(0xffffffffu, ls1, 1);
        ls1 += __shfl_xor_sync(0xffffffffu, ls1, 2);
        lrun0 = lrun0 * corr0 + ls0;
        lrun1 = lrun1 * corr1 + ls1;
#pragma unroll
        for (int nd = 0; nd < 8; nd++) {
            o[nd][0] *= corr0; o[nd][1] *= corr0;
            o[nd][2] *= corr1; o[nd][3] *= corr1;
        }

        // ---- O += P V ----
#pragma unroll
        for (int j = 0; j < 4; j++) {
            // P fragments from s[2j], s[2j+1] (C-layout == A-layout)
            float* pa = s[2 * j];
            float* pb = s[2 * j + 1];
            bf16 h00, h01, h02, h03, h10, h11, h12, h13;
            bf16 l00, l01, l02, l03, l10, l11, l12, l13;
            split2(pa[0], h00, l00); split2(pa[1], h01, l01);
            split2(pa[2], h02, l02); split2(pa[3], h03, l03);
            split2(pb[0], h10, l10); split2(pb[1], h11, l11);
            split2(pb[2], h12, l12); split2(pb[3], h13, l13);
            uint32_t pah[4], pal[4];
            pah[0] = pack_bf2(h00, h01);
            pah[1] = pack_bf2(h02, h03);
            pah[2] = pack_bf2(h10, h11);
            pah[3] = pack_bf2(h12, h13);
            pal[0] = pack_bf2(l00, l01);
            pal[1] = pack_bf2(l02, l03);
            pal[2] = pack_bf2(l10, l11);
            pal[3] = pack_bf2(l12, l13);
#pragma unroll
            for (int nd2 = 0; nd2 < 4; nd2++) {
                uint32_t vh4[4], vl4[4];
                ldmat4t(vh4, sb + A_VH + voffs + j * 2304 + nd2 * 32);
                ldmat4t(vl4, sb + A_VL + voffs + j * 2304 + nd2 * 32);
                mma_bf16(o[2 * nd2],     pah, vh4[0], vh4[1]);
                mma_bf16(o[2 * nd2],     pah, vl4[0], vl4[1]);
                mma_bf16(o[2 * nd2],     pal, vh4[0], vh4[1]);
                mma_bf16(o[2 * nd2 + 1], pah, vh4[2], vh4[3]);
                mma_bf16(o[2 * nd2 + 1], pah, vl4[2], vl4[3]);
                mma_bf16(o[2 * nd2 + 1], pal, vh4[2], vh4[3]);
            }
        }
    }

    // ---- epilogue ----
    float inv0 = 1.f / lrun0, inv1 = 1.f / lrun1;
    int r0 = q0 + w * 16 + (lane >> 2);
    size_t obase = ((size_t)(b * 4096)) * 512 + h * 64;
#pragma unroll
    for (int nd = 0; nd < 8; nd++) {
        int col = nd * 8 + (lane & 3) * 2;
        float2 v0 = {o[nd][0] * inv0, o[nd][1] * inv0};
        float2 v1 = {o[nd][2] * inv1, o[nd][3] * inv1};
        *(float2*)(ao + obase + (size_t)r0 * 512 + col) = v0;
        *(float2*)(ao + obase + (size_t)(r0 + 8) * 512 + col) = v1;
    }
}

// ===========================================================================
// Launch
// ===========================================================================
extern "C" void kernel_launch(void* const* d_in, const int* in_sizes, int n_in,
                              void* d_out, int out_size) {
    (void)in_sizes; (void)n_in; (void)out_size;

    const float* x     = (const float*)d_in[0];
    const float* Wq    = (const float*)d_in[1];
    const float* bq    = (const float*)d_in[2];
    const float* Wkv   = (const float*)d_in[3];
    const float* bkv   = (const float*)d_in[4];
    const float* Wproj = (const float*)d_in[5];
    const float* bproj = (const float*)d_in[6];
    const float* Aq    = (const float*)d_in[7];
    const float* Bq    = (const float*)d_in[8];
    const float* Av    = (const float*)d_in[9];
    const float* Bv    = (const float*)d_in[10];
    const float* Wsr   = (const float*)d_in[11];
    const float* bsr   = (const float*)d_in[12];
    const float* gamma = (const float*)d_in[13];
    const float* beta  = (const float*)d_in[14];
    float* out = (float*)d_out;

    float *qbuf, *xs, *kvbuf, *ao;
    bf16 *xhi, *xlo, *xshi, *xslo, *aohi, *aolo, *qhi, *qlo;
    bf16 *khi, *klo, *vhi, *vlo;
    bf16 *WqTh, *WqTl, *WkvTh, *WkvTl, *WpTh, *WpTl, *WsrTh, *WsrTl;
    cudaGetSymbolAddress((void**)&qbuf,  g_q);
    cudaGetSymbolAddress((void**)&xs,    g_xs);
    cudaGetSymbolAddress((void**)&kvbuf, g_kv);
    cudaGetSymbolAddress((void**)&ao,    g_ao);
    cudaGetSymbolAddress((void**)&xhi,   g_xhi);
    cudaGetSymbolAddress((void**)&xlo,   g_xlo);
    cudaGetSymbolAddress((void**)&xshi,  g_xshi);
    cudaGetSymbolAddress((void**)&xslo,  g_xslo);
    cudaGetSymbolAddress((void**)&aohi,  g_aohi);
    cudaGetSymbolAddress((void**)&aolo,  g_aolo);
    cudaGetSymbolAddress((void**)&qhi,   g_qhi);
    cudaGetSymbolAddress((void**)&qlo,   g_qlo);
    cudaGetSymbolAddress((void**)&khi,   g_khi);
    cudaGetSymbolAddress((void**)&klo,   g_klo);
    cudaGetSymbolAddress((void**)&vhi,   g_vhi);
    cudaGetSymbolAddress((void**)&vlo,   g_vlo);
    cudaGetSymbolAddress((void**)&WqTh,  g_WqTh);
    cudaGetSymbolAddress((void**)&WqTl,  g_WqTl);
    cudaGetSymbolAddress((void**)&WkvTh, g_WkvTh);
    cudaGetSymbolAddress((void**)&WkvTl, g_WkvTl);
    cudaGetSymbolAddress((void**)&WpTh,  g_WpTh);
    cudaGetSymbolAddress((void**)&WpTl,  g_WpTl);
    cudaGetSymbolAddress((void**)&WsrTh, g_WsrTh);
    cudaGetSymbolAddress((void**)&WsrTl, g_WsrTl);

    cudaFuncSetAttribute(gemm_mma<false>, cudaFuncAttributeMaxDynamicSharedMemorySize, G_SMEM);
    cudaFuncSetAttribute(gemm_mma<true>,  cudaFuncAttributeMaxDynamicSharedMemorySize, G_SMEM);
    cudaFuncSetAttribute(attn_mma, cudaFuncAttributeMaxDynamicSharedMemorySize, A_SMEM);

    // weight prep
    prep_wqT_kernel<<<1024, 256>>>(Wq, Aq, Bq, WqTh, WqTl);
    prep_wkvT_kernel<<<2048, 256>>>(Wkv, Av, Bv, WkvTh, WkvTl);
    prep_wpT_kernel<<<1024, 256>>>(Wproj, WpTh, WpTl);
    prep_wsrT_kernel<<<4096, 256>>>(Wsr, WsrTh, WsrTl);

    // split x
    split_kernel<<<4096, 256>>>(x, xhi, xlo);

    // q = x @ WqE + bq   (8192 x 512 x 512)
    gemm_mma<false><<<dim3(64, 4), 256, G_SMEM>>>(xhi, xlo, WqTh, WqTl, bq, qbuf,
                                                  8192, 512, 512);

    // conv as gathered GEMM (2048 x 512 x 2048)
    gemm_mma<true><<<dim3(16, 4), 256, G_SMEM>>>(xhi, xlo, WsrTh, WsrTl, bsr, xs,
                                                 2048, 512, 2048);

    // LN + split xs
    ln_kernel<<<2048, 256>>>(xs, gamma, beta);
    split_kernel<<<1024, 256>>>(xs, xshi, xslo);

    // kv = xs @ WkvE + bkv  (2048 x 1024 x 512)
    gemm_mma<false><<<dim3(16, 8), 256, G_SMEM>>>(xshi, xslo, WkvTh, WkvTl, bkv, kvbuf,
                                                  2048, 1024, 512);

    // splits for attention
    split_kv_kernel<<<1024, 256>>>(kvbuf, khi, klo, vhi, vlo);
    split_scale_kernel<<<4096, 256>>>(qbuf, qhi, qlo);

    // attention
    attn_mma<<<dim3(32, 8, 2), 256, A_SMEM>>>(qhi, qlo, khi, klo, vhi, vlo, ao);

    // proj
    split_kernel<<<4096, 256>>>(ao, aohi, aolo);
    gemm_mma<false><<<dim3(64, 4), 256, G_SMEM>>>(aohi, aolo, WpTh, WpTl, bproj, out,
                                                  8192, 512, 512);
}

// round 6
// speedup vs baseline: 2.4807x; 1.1359x over previous
#include <cuda_runtime.h>
#include <cuda_bf16.h>
#include <math.h>
#include <stddef.h>
#include <stdint.h>

#define LN_EPS 1e-5f
#define LOG2E 1.44269504088896340736f
typedef __nv_bfloat16 bf16;

// ===========================================================================
// Primitives (compute_100 baseline PTX)
// ===========================================================================
__device__ __forceinline__ uint32_t smem_u32(const void* p) {
    uint32_t a;
    asm("{ .reg .u64 t; cvta.to.shared.u64 t, %1; cvt.u32.u64 %0, t; }"
        : "=r"(a) : "l"(p));
    return a;
}

__device__ __forceinline__ void mma_bf16(float* d, const uint32_t* a,
                                         uint32_t b0, uint32_t b1) {
    asm volatile(
        "mma.sync.aligned.m16n8k16.row.col.f32.bf16.bf16.f32 "
        "{%0,%1,%2,%3}, {%4,%5,%6,%7}, {%8,%9}, {%0,%1,%2,%3};"
        : "+f"(d[0]), "+f"(d[1]), "+f"(d[2]), "+f"(d[3])
        : "r"(a[0]), "r"(a[1]), "r"(a[2]), "r"(a[3]), "r"(b0), "r"(b1));
}

__device__ __forceinline__ void ldmat4(uint32_t* r, uint32_t addr) {
    asm volatile("ldmatrix.sync.aligned.m8n8.x4.shared.b16 {%0,%1,%2,%3}, [%4];"
        : "=r"(r[0]), "=r"(r[1]), "=r"(r[2]), "=r"(r[3]) : "r"(addr));
}
__device__ __forceinline__ void ldmat4t(uint32_t* r, uint32_t addr) {
    asm volatile("ldmatrix.sync.aligned.m8n8.x4.trans.shared.b16 {%0,%1,%2,%3}, [%4];"
        : "=r"(r[0]), "=r"(r[1]), "=r"(r[2]), "=r"(r[3]) : "r"(addr));
}

__device__ __forceinline__ void cp16(uint32_t s, const void* g) {
    asm volatile("cp.async.cg.shared.global [%0], [%1], 16;" :: "r"(s), "l"(g));
}
#define CP_COMMIT() asm volatile("cp.async.commit_group;")
#define CP_WAIT(N)  asm volatile("cp.async.wait_group %0;" :: "n"(N))

__device__ __forceinline__ uint32_t pack_bf2(bf16 a, bf16 b) {
    __nv_bfloat162 t(a, b);
    return *reinterpret_cast<uint32_t*>(&t);
}
__device__ __forceinline__ void split2(float v, bf16& h, bf16& l) {
    h = __float2bfloat16(v);
    l = __float2bfloat16(v - __bfloat162float(h));
}
__device__ __forceinline__ void split_pack2(float f0, float f1,
                                            uint32_t& hw, uint32_t& lw) {
    bf16 h0, h1, l0, l1;
    split2(f0, h0, l0); split2(f1, h1, l1);
    hw = pack_bf2(h0, h1);
    lw = pack_bf2(l0, l1);
}

// ===========================================================================
// Scratch
// ===========================================================================
__device__ float g_convp[4 * 2048 * 512];                 // conv partials

__device__ bf16 g_xhi[4194304],  g_xlo[4194304];
__device__ bf16 g_xshi[1048576], g_xslo[1048576];
__device__ bf16 g_aohi[4194304], g_aolo[4194304];
__device__ bf16 g_qhi[4194304],  g_qlo[4194304];          // q * 0.125, split
__device__ bf16 g_khi[1048576],  g_klo[1048576];
__device__ bf16 g_vhi[1048576],  g_vlo[1048576];
__device__ bf16 g_WqTh[262144],  g_WqTl[262144];          // [n][k]
__device__ bf16 g_WkvTh[524288], g_WkvTl[524288];
__device__ bf16 g_WpTh[262144],  g_WpTl[262144];
__device__ bf16 g_WsrTh[1048576], g_WsrTl[1048576];       // [p][n][k]

// ===========================================================================
// Weight prep: fold LoRA, transpose to [n][k], split hi/lo
// ===========================================================================
__global__ void prep_wqT_kernel(const float* __restrict__ Wq,
                                const float* __restrict__ Aq,
                                const float* __restrict__ Bq,
                                bf16* __restrict__ Th, bf16* __restrict__ Tl) {
    int idx = blockIdx.x * blockDim.x + threadIdx.x;
    int n = idx >> 9, k = idx & 511;
    float w = Wq[k * 512 + n];
#pragma unroll
    for (int r = 0; r < 8; r++) w += Aq[k * 8 + r] * Bq[r * 512 + n];
    split2(w, Th[idx], Tl[idx]);
}

__global__ void prep_wkvT_kernel(const float* __restrict__ Wkv,
                                 const float* __restrict__ Av,
                                 const float* __restrict__ Bv,
                                 bf16* __restrict__ Th, bf16* __restrict__ Tl) {
    int idx = blockIdx.x * blockDim.x + threadIdx.x;   // idx = n*512+k, n<1024
    int n = idx >> 9, k = idx & 511, ln = n & 511;
    float w = Wkv[k * 1024 + n];
#pragma unroll
    for (int r = 0; r < 8; r++) w += Av[k * 8 + r] * Bv[r * 512 + ln];
    split2(w, Th[idx], Tl[idx]);
}

__global__ void prep_wpT_kernel(const float* __restrict__ Wp,
                                bf16* __restrict__ Th, bf16* __restrict__ Tl) {
    int idx = blockIdx.x * blockDim.x + threadIdx.x;
    int n = idx >> 9, k = idx & 511;
    split2(Wp[k * 512 + n], Th[idx], Tl[idx]);
}

__global__ void prep_wsrT_kernel(const float* __restrict__ Wsr,
                                 bf16* __restrict__ Th, bf16* __restrict__ Tl) {
    int idx = blockIdx.x * blockDim.x + threadIdx.x;   // (p*512+n)*512+k
    int p = idx >> 18, rem = idx & 262143;
    int n = rem >> 9, k = rem & 511;
    split2(Wsr[(size_t)p * 262144 + k * 512 + n], Th[idx], Tl[idx]);
}

// split x (only remaining standalone split)
__global__ void split_kernel(const float* __restrict__ src,
                             bf16* __restrict__ hi, bf16* __restrict__ lo) {
    int i = blockIdx.x * blockDim.x + threadIdx.x;
    float4 v = ((const float4*)src)[i];
    uint32_t h0, l0, h1, l1;
    split_pack2(v.x, v.y, h0, l0);
    split_pack2(v.z, v.w, h1, l1);
    ((uint32_t*)hi)[i * 2] = h0; ((uint32_t*)hi)[i * 2 + 1] = h1;
    ((uint32_t*)lo)[i * 2] = l0; ((uint32_t*)lo)[i * 2 + 1] = l1;
}

// ===========================================================================
// mma.sync GEMM, bf16x3: C = A @ B^T (+bias). Tile 128x128, Kchunk 32, 8 warps.
// MODE 0: fp32 out + bias                   (proj)
// MODE 1: conv split-K: patch p=blockIdx.z, K=512, fp32 partial, no bias
// MODE 2: bf16 hi/lo out, (acc+bias)*0.125  (q)
// MODE 3: bf16 hi/lo out to k/v arrays      (kv, N=1024)
// ===========================================================================
#define G_STAGE 40960   // 4 tiles x 128 rows x 40 bf16 (80 B)
#define G_TA_HI 0
#define G_TA_LO 10240
#define G_TB_HI 20480
#define G_TB_LO 30720
#define G_SMEM  (2 * G_STAGE)

template <int MODE>
__global__ __launch_bounds__(256)
void gemm_mma(const bf16* __restrict__ Ah, const bf16* __restrict__ Al,
              const bf16* __restrict__ Bh, const bf16* __restrict__ Bl,
              const float* __restrict__ bias, float* __restrict__ C,
              bf16* __restrict__ H1, bf16* __restrict__ L1,
              bf16* __restrict__ H2, bf16* __restrict__ L2,
              int M, int N, int K) {
    extern __shared__ __align__(16) char smem[];
    uint32_t sb = smem_u32(smem);
    int tid = threadIdx.x, lane = tid & 31, w = tid >> 5;
    int wm = w & 3, wn = w >> 2;
    int m0 = blockIdx.x * 128, n0 = blockIdx.y * 128;
    int p = (MODE == 1) ? blockIdx.z : 0;
    int nch = K >> 5;

    float acc[2][8][4] = {};

    auto issue = [&](int c) {
        uint32_t sbase = sb + (c & 1) * G_STAGE;
#pragma unroll
        for (int i = 0; i < 2; i++) {
            int idx = tid + i * 256;
            int r = idx >> 2, g = idx & 3;
            uint32_t dst = (uint32_t)(r * 80 + g * 16);
            size_t aoff, boff;
            if (MODE == 1) {
                int koff = c * 32 + g * 8;
                int m = m0 + r;
                int bb = m >> 10, s = m & 1023;
                int oh = s >> 5, ow = s & 31;
                int xr = (2 * oh + (p >> 1)) * 64 + 2 * ow + (p & 1);
                aoff = ((size_t)(bb * 4096 + xr)) * 512 + koff;
                boff = ((size_t)(p * 512 + n0 + r)) * 512 + koff;
            } else {
                aoff = (size_t)(m0 + r) * K + c * 32 + g * 8;
                boff = (size_t)(n0 + r) * K + c * 32 + g * 8;
            }
            cp16(sbase + G_TA_HI + dst, Ah + aoff);
            cp16(sbase + G_TA_LO + dst, Al + aoff);
            cp16(sbase + G_TB_HI + dst, Bh + boff);
            cp16(sbase + G_TB_LO + dst, Bl + boff);
        }
    };

    uint32_t aoffs = (uint32_t)((wm * 32 + (lane & 15)) * 80 + (lane >> 4) * 16);
    uint32_t boffs = (uint32_t)((wn * 64 + ((lane >> 4) & 1) * 8 + (lane & 7)) * 80
                                + ((lane >> 3) & 1) * 16);

    issue(0); CP_COMMIT();

    for (int c = 0; c < nch; c++) {
        if (c + 1 < nch) { issue(c + 1); CP_COMMIT(); CP_WAIT(1); }
        else             { CP_WAIT(0); }
        __syncthreads();

        uint32_t sbase = sb + (c & 1) * G_STAGE;
#pragma unroll
        for (int ks = 0; ks < 2; ks++) {
            uint32_t ah[2][4], al[2][4];
#pragma unroll
            for (int mi = 0; mi < 2; mi++) {
                ldmat4(ah[mi], sbase + G_TA_HI + aoffs + mi * 1280 + ks * 32);
                ldmat4(al[mi], sbase + G_TA_LO + aoffs + mi * 1280 + ks * 32);
            }
#pragma unroll
            for (int jj = 0; jj < 4; jj++) {
                uint32_t bh4[4], bl4[4];
                ldmat4(bh4, sbase + G_TB_HI + boffs + jj * 1280 + ks * 32);
                ldmat4(bl4, sbase + G_TB_LO + boffs + jj * 1280 + ks * 32);
#pragma unroll
                for (int mi = 0; mi < 2; mi++) {
                    mma_bf16(acc[mi][2 * jj],     ah[mi], bh4[0], bh4[1]);
                    mma_bf16(acc[mi][2 * jj],     ah[mi], bl4[0], bl4[1]);
                    mma_bf16(acc[mi][2 * jj],     al[mi], bh4[0], bh4[1]);
                    mma_bf16(acc[mi][2 * jj + 1], ah[mi], bh4[2], bh4[3]);
                    mma_bf16(acc[mi][2 * jj + 1], ah[mi], bl4[2], bl4[3]);
                    mma_bf16(acc[mi][2 * jj + 1], al[mi], bh4[2], bh4[3]);
                }
            }
        }
        __syncthreads();
    }

    // ---- epilogue ----
#pragma unroll
    for (int mi = 0; mi < 2; mi++) {
        int row = m0 + wm * 32 + mi * 16 + (lane >> 2);
#pragma unroll
        for (int nj = 0; nj < 8; nj++) {
            int col = n0 + wn * 64 + nj * 8 + (lane & 3) * 2;
            if (MODE == 0) {
                float b0 = bias[col], b1 = bias[col + 1];
                float2 v0 = {acc[mi][nj][0] + b0, acc[mi][nj][1] + b1};
                float2 v1 = {acc[mi][nj][2] + b0, acc[mi][nj][3] + b1};
                *(float2*)&C[(size_t)row * N + col] = v0;
                *(float2*)&C[(size_t)(row + 8) * N + col] = v1;
            } else if (MODE == 1) {
                float* out = C + (size_t)p * 2048 * 512;
                float2 v0 = {acc[mi][nj][0], acc[mi][nj][1]};
                float2 v1 = {acc[mi][nj][2], acc[mi][nj][3]};
                *(float2*)&out[(size_t)row * N + col] = v0;
                *(float2*)&out[(size_t)(row + 8) * N + col] = v1;
            } else if (MODE == 2) {
                float b0 = bias[col], b1 = bias[col + 1];
                uint32_t hw, lw;
                split_pack2((acc[mi][nj][0] + b0) * 0.125f,
                            (acc[mi][nj][1] + b1) * 0.125f, hw, lw);
                *(uint32_t*)&H1[(size_t)row * N + col] = hw;
                *(uint32_t*)&L1[(size_t)row * N + col] = lw;
                split_pack2((acc[mi][nj][2] + b0) * 0.125f,
                            (acc[mi][nj][3] + b1) * 0.125f, hw, lw);
                *(uint32_t*)&H1[(size_t)(row + 8) * N + col] = hw;
                *(uint32_t*)&L1[(size_t)(row + 8) * N + col] = lw;
            } else {  // MODE 3: kv
                float b0 = bias[col], b1 = bias[col + 1];
                bf16* Hd = (col < 512) ? H1 : H2;
                bf16* Ld = (col < 512) ? L1 : L2;
                int c2 = col & 511;
                uint32_t hw, lw;
                split_pack2(acc[mi][nj][0] + b0, acc[mi][nj][1] + b1, hw, lw);
                *(uint32_t*)&Hd[(size_t)row * 512 + c2] = hw;
                *(uint32_t*)&Ld[(size_t)row * 512 + c2] = lw;
                split_pack2(acc[mi][nj][2] + b0, acc[mi][nj][3] + b1, hw, lw);
                *(uint32_t*)&Hd[(size_t)(row + 8) * 512 + c2] = hw;
                *(uint32_t*)&Ld[(size_t)(row + 8) * 512 + c2] = lw;
            }
        }
    }
}

// ===========================================================================
// Sum conv partials + bias, LayerNorm, write bf16 hi/lo directly
// ===========================================================================
__global__ void ln_fuse_kernel(const float* __restrict__ part,
                               const float* __restrict__ bsr,
                               const float* __restrict__ gamma,
                               const float* __restrict__ beta,
                               bf16* __restrict__ xsh, bf16* __restrict__ xsl) {
    __shared__ float red[256];
    __shared__ float s_mean, s_inv;
    const size_t RS = (size_t)2048 * 512;
    int t = threadIdx.x;
    size_t ro = (size_t)blockIdx.x * 512;

    float v0 = part[ro + t] + part[RS + ro + t] + part[2 * RS + ro + t] +
               part[3 * RS + ro + t] + bsr[t];
    int t2 = t + 256;
    float v1 = part[ro + t2] + part[RS + ro + t2] + part[2 * RS + ro + t2] +
               part[3 * RS + ro + t2] + bsr[t2];

    red[t] = v0 + v1;
    __syncthreads();
    for (int off = 128; off; off >>= 1) {
        if (t < off) red[t] += red[t + off];
        __syncthreads();
    }
    if (t == 0) s_mean = red[0] * (1.f / 512.f);
    __syncthreads();
    float mean = s_mean;
    float d0 = v0 - mean, d1 = v1 - mean;
    red[t] = d0 * d0 + d1 * d1;
    __syncthreads();
    for (int off = 128; off; off >>= 1) {
        if (t < off) red[t] += red[t + off];
        __syncthreads();
    }
    if (t == 0) s_inv = rsqrtf(red[0] * (1.f / 512.f) + LN_EPS);
    __syncthreads();
    float inv = s_inv;
    float y0 = d0 * inv * gamma[t]  + beta[t];
    float y1 = d1 * inv * gamma[t2] + beta[t2];
    split2(y0, xsh[ro + t],  xsl[ro + t]);
    split2(y1, xsh[ro + t2], xsl[ro + t2]);
}

// ===========================================================================
// Flash attention, mma.sync bf16x3, cp.async double-buffered KV.
// Block: 128 q rows x (b,h); 8 warps. kv = 16 tiles of 64.
// smem: QH/QL [128][72] at 0/18432; 2 KV stages of 36864 B at 36864
//   (within stage: KH 0, KL 9216, VH 18432, VL 27648; row stride 144 B)
// ===========================================================================
#define P_QH  0
#define P_QL  18432
#define P_KV  36864
#define P_STG 36864
#define S_KH  0
#define S_KL  9216
#define S_VH  18432
#define S_VL  27648
#define A_SMEM (P_KV + 2 * P_STG)

__global__ __launch_bounds__(256)
void attn_mma(const bf16* __restrict__ qh, const bf16* __restrict__ ql,
              const bf16* __restrict__ kh, const bf16* __restrict__ kl,
              const bf16* __restrict__ vh, const bf16* __restrict__ vl,
              bf16* __restrict__ aoh, bf16* __restrict__ aol) {
    extern __shared__ __align__(16) char smem[];
    uint32_t sb = smem_u32(smem);
    int tid = threadIdx.x, lane = tid & 31, w = tid >> 5;
    int b = blockIdx.z, h = blockIdx.y;
    int q0 = blockIdx.x * 128;

    size_t kvbase = ((size_t)b * 1024) * 512 + h * 64;

    auto issue_kv = [&](int t) {
        char* stg = smem + P_KV + (t & 1) * P_STG;
        uint32_t su = sb + P_KV + (t & 1) * P_STG;
        (void)stg;
#pragma unroll
        for (int i = 0; i < 2; i++) {
            int idx = tid + i * 256;          // 512: 64 rows x 8 chunks
            int r = idx >> 3, g = idx & 7;
            uint32_t dst = (uint32_t)(r * 144 + g * 16);
            size_t src = kvbase + (size_t)(t * 64 + r) * 512 + g * 8;
            cp16(su + S_KH + dst, kh + src);
            cp16(su + S_KL + dst, kl + src);
            cp16(su + S_VH + dst, vh + src);
            cp16(su + S_VL + dst, vl + src);
        }
    };

    // prefetch KV tile 0 while loading Q
    issue_kv(0); CP_COMMIT();

    size_t qbase = ((size_t)(b * 4096 + q0)) * 512 + h * 64;
#pragma unroll
    for (int i = 0; i < 4; i++) {
        int idx = tid + i * 256;
        int r = idx >> 3, g = idx & 7;
        uint32_t dst = (uint32_t)(r * 144 + g * 16);
        size_t src = qbase + (size_t)r * 512 + g * 8;
        *(uint4*)(smem + P_QH + dst) = *(const uint4*)(qh + src);
        *(uint4*)(smem + P_QL + dst) = *(const uint4*)(ql + src);
    }
    __syncthreads();

    uint32_t qf_h[4][4], qf_l[4][4];
    uint32_t qoffs = (uint32_t)((w * 16 + (lane & 15)) * 144 + (lane >> 4) * 16);
#pragma unroll
    for (int ks = 0; ks < 4; ks++) {
        ldmat4(qf_h[ks], sb + P_QH + qoffs + ks * 32);
        ldmat4(qf_l[ks], sb + P_QL + qoffs + ks * 32);
    }

    float o[8][4] = {};
    float mrun0 = -3.0e38f, mrun1 = -3.0e38f, lrun0 = 0.f, lrun1 = 0.f;

    uint32_t koffs = (uint32_t)((((lane >> 4) & 1) * 8 + (lane & 7)) * 144
                                + ((lane >> 3) & 1) * 16);
    uint32_t voffs = (uint32_t)((((lane >> 3) & 1) * 8 + (lane & 7)) * 144
                                + (lane >> 4) * 16);

    for (int t = 0; t < 16; t++) {
        if (t + 1 < 16) { issue_kv(t + 1); CP_COMMIT(); CP_WAIT(1); }
        else            { CP_WAIT(0); }
        __syncthreads();

        uint32_t stg = sb + P_KV + (t & 1) * P_STG;

        // ---- S = Q K^T ----
        float s[8][4] = {};
#pragma unroll
        for (int ks = 0; ks < 4; ks++) {
#pragma unroll
            for (int jj = 0; jj < 4; jj++) {
                uint32_t bh4[4], bl4[4];
                ldmat4(bh4, stg + S_KH + koffs + jj * 2304 + ks * 32);
                ldmat4(bl4, stg + S_KL + koffs + jj * 2304 + ks * 32);
                mma_bf16(s[2 * jj],     qf_h[ks], bh4[0], bh4[1]);
                mma_bf16(s[2 * jj],     qf_h[ks], bl4[0], bl4[1]);
                mma_bf16(s[2 * jj],     qf_l[ks], bh4[0], bh4[1]);
                mma_bf16(s[2 * jj + 1], qf_h[ks], bh4[2], bh4[3]);
                mma_bf16(s[2 * jj + 1], qf_h[ks], bl4[2], bl4[3]);
                mma_bf16(s[2 * jj + 1], qf_l[ks], bh4[2], bh4[3]);
            }
        }

        // ---- online softmax ----
        float tm0 = -3.0e38f, tm1 = -3.0e38f;
#pragma unroll
        for (int nj = 0; nj < 8; nj++) {
            tm0 = fmaxf(tm0, fmaxf(s[nj][0], s[nj][1]));
            tm1 = fmaxf(tm1, fmaxf(s[nj][2], s[nj][3]));
        }
        tm0 = fmaxf(tm0, __shfl_xor_sync(0xffffffffu, tm0, 1));
        tm0 = fmaxf(tm0, __shfl_xor_sync(0xffffffffu, tm0, 2));
        tm1 = fmaxf(tm1, __shfl_xor_sync(0xffffffffu, tm1, 1));
        tm1 = fmaxf(tm1, __shfl_xor_sync(0xffffffffu, tm1, 2));
        float mn0 = fmaxf(mrun0, tm0), mn1 = fmaxf(mrun1, tm1);
        float corr0 = exp2f((mrun0 - mn0) * LOG2E);
        float corr1 = exp2f((mrun1 - mn1) * LOG2E);
        mrun0 = mn0; mrun1 = mn1;
        float ls0 = 0.f, ls1 = 0.f;
#pragma unroll
        for (int nj = 0; nj < 8; nj++) {
            s[nj][0] = exp2f((s[nj][0] - mn0) * LOG2E);
            s[nj][1] = exp2f((s[nj][1] - mn0) * LOG2E);
            s[nj][2] = exp2f((s[nj][2] - mn1) * LOG2E);
            s[nj][3] = exp2f((s[nj][3] - mn1) * LOG2E);
            ls0 += s[nj][0] + s[nj][1];
            ls1 += s[nj][2] + s[nj][3];
        }
        ls0 += __shfl_xor_sync(0xffffffffu, ls0, 1);
        ls0 += __shfl_xor_sync(0xffffffffu, ls0, 2);
        ls1 += __shfl_xor_sync(0xffffffffu, ls1, 1);
        ls1 += __shfl_xor_sync(0xffffffffu, ls1, 2);
        lrun0 = lrun0 * corr0 + ls0;
        lrun1 = lrun1 * corr1 + ls1;
#pragma unroll
        for (int nd = 0; nd < 8; nd++) {
            o[nd][0] *= corr0; o[nd][1] *= corr0;
            o[nd][2] *= corr1; o[nd][3] *= corr1;
        }

        // ---- O += P V ----
#pragma unroll
        for (int j = 0; j < 4; j++) {
            float* pa = s[2 * j];
            float* pb = s[2 * j + 1];
            bf16 h00, h01, h02, h03, h10, h11, h12, h13;
            bf16 l00, l01, l02, l03, l10, l11, l12, l13;
            split2(pa[0], h00, l00); split2(pa[1], h01, l01);
            split2(pa[2], h02, l02); split2(pa[3], h03, l03);
            split2(pb[0], h10, l10); split2(pb[1], h11, l11);
            split2(pb[2], h12, l12); split2(pb[3], h13, l13);
            uint32_t pah[4], pal[4];
            pah[0] = pack_bf2(h00, h01);
            pah[1] = pack_bf2(h02, h03);
            pah[2] = pack_bf2(h10, h11);
            pah[3] = pack_bf2(h12, h13);
            pal[0] = pack_bf2(l00, l01);
            pal[1] = pack_bf2(l02, l03);
            pal[2] = pack_bf2(l10, l11);
            pal[3] = pack_bf2(l12, l13);
#pragma unroll
            for (int nd2 = 0; nd2 < 4; nd2++) {
                uint32_t vh4[4], vl4[4];
                ldmat4t(vh4, stg + S_VH + voffs + j * 2304 + nd2 * 32);
                ldmat4t(vl4, stg + S_VL + voffs + j * 2304 + nd2 * 32);
                mma_bf16(o[2 * nd2],     pah, vh4[0], vh4[1]);
                mma_bf16(o[2 * nd2],     pah, vl4[0], vl4[1]);
                mma_bf16(o[2 * nd2],     pal, vh4[0], vh4[1]);
                mma_bf16(o[2 * nd2 + 1], pah, vh4[2], vh4[3]);
                mma_bf16(o[2 * nd2 + 1], pah, vl4[2], vl4[3]);
                mma_bf16(o[2 * nd2 + 1], pal, vh4[2], vh4[3]);
            }
        }
        __syncthreads();
    }

    // ---- epilogue: write bf16 hi/lo directly ----
    float inv0 = 1.f / lrun0, inv1 = 1.f / lrun1;
    int r0 = q0 + w * 16 + (lane >> 2);
    size_t obase = ((size_t)(b * 4096)) * 512 + h * 64;
#pragma unroll
    for (int nd = 0; nd < 8; nd++) {
        int col = nd * 8 + (lane & 3) * 2;
        uint32_t hw, lw;
        split_pack2(o[nd][0] * inv0, o[nd][1] * inv0, hw, lw);
        *(uint32_t*)&aoh[obase + (size_t)r0 * 512 + col] = hw;
        *(uint32_t*)&aol[obase + (size_t)r0 * 512 + col] = lw;
        split_pack2(o[nd][2] * inv1, o[nd][3] * inv1, hw, lw);
        *(uint32_t*)&aoh[obase + (size_t)(r0 + 8) * 512 + col] = hw;
        *(uint32_t*)&aol[obase + (size_t)(r0 + 8) * 512 + col] = lw;
    }
}

// ===========================================================================
// Launch
// ===========================================================================
extern "C" void kernel_launch(void* const* d_in, const int* in_sizes, int n_in,
                              void* d_out, int out_size) {
    (void)in_sizes; (void)n_in; (void)out_size;

    const float* x     = (const float*)d_in[0];
    const float* Wq    = (const float*)d_in[1];
    const float* bq    = (const float*)d_in[2];
    const float* Wkv   = (const float*)d_in[3];
    const float* bkv   = (const float*)d_in[4];
    const float* Wproj = (const float*)d_in[5];
    const float* bproj = (const float*)d_in[6];
    const float* Aq    = (const float*)d_in[7];
    const float* Bq    = (const float*)d_in[8];
    const float* Av    = (const float*)d_in[9];
    const float* Bv    = (const float*)d_in[10];
    const float* Wsr   = (const float*)d_in[11];
    const float* bsr   = (const float*)d_in[12];
    const float* gamma = (const float*)d_in[13];
    const float* beta  = (const float*)d_in[14];
    float* out = (float*)d_out;

    float *convp;
    bf16 *xhi, *xlo, *xshi, *xslo, *aohi, *aolo, *qhi, *qlo;
    bf16 *khi, *klo, *vhi, *vlo;
    bf16 *WqTh, *WqTl, *WkvTh, *WkvTl, *WpTh, *WpTl, *WsrTh, *WsrTl;
    cudaGetSymbolAddress((void**)&convp, g_convp);
    cudaGetSymbolAddress((void**)&xhi,   g_xhi);
    cudaGetSymbolAddress((void**)&xlo,   g_xlo);
    cudaGetSymbolAddress((void**)&xshi,  g_xshi);
    cudaGetSymbolAddress((void**)&xslo,  g_xslo);
    cudaGetSymbolAddress((void**)&aohi,  g_aohi);
    cudaGetSymbolAddress((void**)&aolo,  g_aolo);
    cudaGetSymbolAddress((void**)&qhi,   g_qhi);
    cudaGetSymbolAddress((void**)&qlo,   g_qlo);
    cudaGetSymbolAddress((void**)&khi,   g_khi);
    cudaGetSymbolAddress((void**)&klo,   g_klo);
    cudaGetSymbolAddress((void**)&vhi,   g_vhi);
    cudaGetSymbolAddress((void**)&vlo,   g_vlo);
    cudaGetSymbolAddress((void**)&WqTh,  g_WqTh);
    cudaGetSymbolAddress((void**)&WqTl,  g_WqTl);
    cudaGetSymbolAddress((void**)&WkvTh, g_WkvTh);
    cudaGetSymbolAddress((void**)&WkvTl, g_WkvTl);
    cudaGetSymbolAddress((void**)&WpTh,  g_WpTh);
    cudaGetSymbolAddress((void**)&WpTl,  g_WpTl);
    cudaGetSymbolAddress((void**)&WsrTh, g_WsrTh);
    cudaGetSymbolAddress((void**)&WsrTl, g_WsrTl);

    cudaFuncSetAttribute(gemm_mma<0>, cudaFuncAttributeMaxDynamicSharedMemorySize, G_SMEM);
    cudaFuncSetAttribute(gemm_mma<1>, cudaFuncAttributeMaxDynamicSharedMemorySize, G_SMEM);
    cudaFuncSetAttribute(gemm_mma<2>, cudaFuncAttributeMaxDynamicSharedMemorySize, G_SMEM);
    cudaFuncSetAttribute(gemm_mma<3>, cudaFuncAttributeMaxDynamicSharedMemorySize, G_SMEM);
    cudaFuncSetAttribute(attn_mma, cudaFuncAttributeMaxDynamicSharedMemorySize, A_SMEM);

    // weight prep
    prep_wqT_kernel<<<1024, 256>>>(Wq, Aq, Bq, WqTh, WqTl);
    prep_wkvT_kernel<<<2048, 256>>>(Wkv, Av, Bv, WkvTh, WkvTl);
    prep_wpT_kernel<<<1024, 256>>>(Wproj, WpTh, WpTl);
    prep_wsrT_kernel<<<4096, 256>>>(Wsr, WsrTh, WsrTl);

    // split x
    split_kernel<<<4096, 256>>>(x, xhi, xlo);

    // q GEMM -> qhi/qlo (scaled)   (8192 x 512 x 512)
    gemm_mma<2><<<dim3(64, 4), 256, G_SMEM>>>(xhi, xlo, WqTh, WqTl, bq,
                                              nullptr, qhi, qlo, nullptr, nullptr,
                                              8192, 512, 512);

    // conv split-K by patch -> partials   (2048 x 512 x 512 per patch)
    gemm_mma<1><<<dim3(16, 4, 4), 256, G_SMEM>>>(xhi, xlo, WsrTh, WsrTl, nullptr,
                                                 convp, nullptr, nullptr, nullptr, nullptr,
                                                 2048, 512, 512);

    // sum partials + bias + LN -> xshi/xslo
    ln_fuse_kernel<<<2048, 256>>>(convp, bsr, gamma, beta, xshi, xslo);

    // kv GEMM -> k/v hi/lo   (2048 x 1024 x 512)
    gemm_mma<3><<<dim3(16, 8), 256, G_SMEM>>>(xshi, xslo, WkvTh, WkvTl, bkv,
                                              nullptr, khi, klo, vhi, vlo,
                                              2048, 1024, 512);

    // attention -> aohi/aolo
    attn_mma<<<dim3(32, 8, 2), 256, A_SMEM>>>(qhi, qlo, khi, klo, vhi, vlo, aohi, aolo);

    // proj -> out   (8192 x 512 x 512)
    gemm_mma<0><<<dim3(64, 4), 256, G_SMEM>>>(aohi, aolo, WpTh, WpTl, bproj,
                                              out, nullptr, nullptr, nullptr, nullptr,
                                              8192, 512, 512);
}

// round 7
// speedup vs baseline: 2.7291x; 1.1001x over previous
#include <cuda_runtime.h>
#include <cuda_bf16.h>
#include <math.h>
#include <stddef.h>
#include <stdint.h>

#define LN_EPS 1e-5f
#define LOG2E 1.44269504088896340736f
typedef __nv_bfloat16 bf16;

// ===========================================================================
// Primitives (compute_100 baseline PTX)
// ===========================================================================
__device__ __forceinline__ uint32_t smem_u32(const void* p) {
    uint32_t a;
    asm("{ .reg .u64 t; cvta.to.shared.u64 t, %1; cvt.u32.u64 %0, t; }"
        : "=r"(a) : "l"(p));
    return a;
}

__device__ __forceinline__ void mma_bf16(float* d, const uint32_t* a,
                                         uint32_t b0, uint32_t b1) {
    asm volatile(
        "mma.sync.aligned.m16n8k16.row.col.f32.bf16.bf16.f32 "
        "{%0,%1,%2,%3}, {%4,%5,%6,%7}, {%8,%9}, {%0,%1,%2,%3};"
        : "+f"(d[0]), "+f"(d[1]), "+f"(d[2]), "+f"(d[3])
        : "r"(a[0]), "r"(a[1]), "r"(a[2]), "r"(a[3]), "r"(b0), "r"(b1));
}

__device__ __forceinline__ void ldmat4(uint32_t* r, uint32_t addr) {
    asm volatile("ldmatrix.sync.aligned.m8n8.x4.shared.b16 {%0,%1,%2,%3}, [%4];"
        : "=r"(r[0]), "=r"(r[1]), "=r"(r[2]), "=r"(r[3]) : "r"(addr));
}
__device__ __forceinline__ void ldmat4t(uint32_t* r, uint32_t addr) {
    asm volatile("ldmatrix.sync.aligned.m8n8.x4.trans.shared.b16 {%0,%1,%2,%3}, [%4];"
        : "=r"(r[0]), "=r"(r[1]), "=r"(r[2]), "=r"(r[3]) : "r"(addr));
}

__device__ __forceinline__ void cp16(uint32_t s, const void* g) {
    asm volatile("cp.async.cg.shared.global [%0], [%1], 16;" :: "r"(s), "l"(g));
}
#define CP_COMMIT() asm volatile("cp.async.commit_group;")
#define CP_WAIT(N)  asm volatile("cp.async.wait_group %0;" :: "n"(N))

__device__ __forceinline__ uint32_t pack_bf2(bf16 a, bf16 b) {
    __nv_bfloat162 t(a, b);
    return *reinterpret_cast<uint32_t*>(&t);
}
__device__ __forceinline__ void split2(float v, bf16& h, bf16& l) {
    h = __float2bfloat16(v);
    l = __float2bfloat16(v - __bfloat162float(h));
}
__device__ __forceinline__ void split_pack2(float f0, float f1,
                                            uint32_t& hw, uint32_t& lw) {
    bf16 h0, h1, l0, l1;
    split2(f0, h0, l0); split2(f1, h1, l1);
    hw = pack_bf2(h0, h1);
    lw = pack_bf2(l0, l1);
}

// ===========================================================================
// Scratch
// ===========================================================================
__device__ float g_convp[4 * 2048 * 512];                 // conv partials

__device__ bf16 g_xhi[4194304],  g_xlo[4194304];
__device__ bf16 g_xshi[1048576], g_xslo[1048576];
__device__ bf16 g_aohi[4194304], g_aolo[4194304];
__device__ bf16 g_qhi[4194304],  g_qlo[4194304];          // q * 0.125, split
__device__ bf16 g_khi[1048576],  g_klo[1048576];
__device__ bf16 g_vhi[1048576],  g_vlo[1048576];
__device__ bf16 g_WqTh[262144],  g_WqTl[262144];          // [n][k]
__device__ bf16 g_WkvTh[524288], g_WkvTl[524288];
__device__ bf16 g_WpTh[262144],  g_WpTl[262144];
__device__ bf16 g_WsrTh[1048576], g_WsrTl[1048576];       // [p][n][k]

// ===========================================================================
// Weight prep: tiled smem transposes (coalesced reads AND writes)
// block dim3(32,8); 32x32 tile per block
// ===========================================================================
__global__ void prep_wqT_kernel(const float* __restrict__ Wq,
                                const float* __restrict__ Aq,
                                const float* __restrict__ Bq,
                                bf16* __restrict__ Th, bf16* __restrict__ Tl) {
    __shared__ bf16 th[32][33], tl[32][33];
    int tx = threadIdx.x, ty = threadIdx.y;
    int n0 = blockIdx.x * 32, k0 = blockIdx.y * 32;
#pragma unroll
    for (int i = 0; i < 4; i++) {
        int k = k0 + ty + i * 8, n = n0 + tx;
        float w = Wq[k * 512 + n];
#pragma unroll
        for (int r = 0; r < 8; r++) w += Aq[k * 8 + r] * Bq[r * 512 + n];
        bf16 h, l; split2(w, h, l);
        th[ty + i * 8][tx] = h; tl[ty + i * 8][tx] = l;
    }
    __syncthreads();
#pragma unroll
    for (int i = 0; i < 4; i++) {
        int n = n0 + ty + i * 8, k = k0 + tx;
        Th[n * 512 + k] = th[tx][ty + i * 8];
        Tl[n * 512 + k] = tl[tx][ty + i * 8];
    }
}

__global__ void prep_wkvT_kernel(const float* __restrict__ Wkv,
                                 const float* __restrict__ Av,
                                 const float* __restrict__ Bv,
                                 bf16* __restrict__ Th, bf16* __restrict__ Tl) {
    __shared__ bf16 th[32][33], tl[32][33];
    int tx = threadIdx.x, ty = threadIdx.y;
    int n0 = blockIdx.x * 32, k0 = blockIdx.y * 32;   // n < 1024
#pragma unroll
    for (int i = 0; i < 4; i++) {
        int k = k0 + ty + i * 8, n = n0 + tx;
        float w = Wkv[k * 1024 + n];
        int ln = n & 511;
#pragma unroll
        for (int r = 0; r < 8; r++) w += Av[k * 8 + r] * Bv[r * 512 + ln];
        bf16 h, l; split2(w, h, l);
        th[ty + i * 8][tx] = h; tl[ty + i * 8][tx] = l;
    }
    __syncthreads();
#pragma unroll
    for (int i = 0; i < 4; i++) {
        int n = n0 + ty + i * 8, k = k0 + tx;
        Th[n * 512 + k] = th[tx][ty + i * 8];
        Tl[n * 512 + k] = tl[tx][ty + i * 8];
    }
}

__global__ void prep_wpT_kernel(const float* __restrict__ Wp,
                                bf16* __restrict__ Th, bf16* __restrict__ Tl) {
    __shared__ bf16 th[32][33], tl[32][33];
    int tx = threadIdx.x, ty = threadIdx.y;
    int n0 = blockIdx.x * 32, k0 = blockIdx.y * 32;
#pragma unroll
    for (int i = 0; i < 4; i++) {
        int k = k0 + ty + i * 8, n = n0 + tx;
        bf16 h, l; split2(Wp[k * 512 + n], h, l);
        th[ty + i * 8][tx] = h; tl[ty + i * 8][tx] = l;
    }
    __syncthreads();
#pragma unroll
    for (int i = 0; i < 4; i++) {
        int n = n0 + ty + i * 8, k = k0 + tx;
        Th[n * 512 + k] = th[tx][ty + i * 8];
        Tl[n * 512 + k] = tl[tx][ty + i * 8];
    }
}

__global__ void prep_wsrT_kernel(const float* __restrict__ Wsr,
                                 bf16* __restrict__ Th, bf16* __restrict__ Tl) {
    __shared__ bf16 th[32][33], tl[32][33];
    int tx = threadIdx.x, ty = threadIdx.y;
    int n0 = blockIdx.x * 32, k0 = blockIdx.y * 32;
    size_t pb = (size_t)blockIdx.z * 262144;
#pragma unroll
    for (int i = 0; i < 4; i++) {
        int k = k0 + ty + i * 8, n = n0 + tx;
        bf16 h, l; split2(Wsr[pb + k * 512 + n], h, l);
        th[ty + i * 8][tx] = h; tl[ty + i * 8][tx] = l;
    }
    __syncthreads();
#pragma unroll
    for (int i = 0; i < 4; i++) {
        int n = n0 + ty + i * 8, k = k0 + tx;
        Th[pb + n * 512 + k] = th[tx][ty + i * 8];
        Tl[pb + n * 512 + k] = tl[tx][ty + i * 8];
    }
}

// split x
__global__ void split_kernel(const float* __restrict__ src,
                             bf16* __restrict__ hi, bf16* __restrict__ lo) {
    int i = blockIdx.x * blockDim.x + threadIdx.x;
    float4 v = ((const float4*)src)[i];
    uint32_t h0, l0, h1, l1;
    split_pack2(v.x, v.y, h0, l0);
    split_pack2(v.z, v.w, h1, l1);
    ((uint32_t*)hi)[i * 2] = h0; ((uint32_t*)hi)[i * 2 + 1] = h1;
    ((uint32_t*)lo)[i * 2] = l0; ((uint32_t*)lo)[i * 2 + 1] = l1;
}

// ===========================================================================
// mma.sync GEMM, bf16x3 (unchanged from round 6)
// ===========================================================================
#define G_STAGE 40960
#define G_TA_HI 0
#define G_TA_LO 10240
#define G_TB_HI 20480
#define G_TB_LO 30720
#define G_SMEM  (2 * G_STAGE)

template <int MODE>
__global__ __launch_bounds__(256)
void gemm_mma(const bf16* __restrict__ Ah, const bf16* __restrict__ Al,
              const bf16* __restrict__ Bh, const bf16* __restrict__ Bl,
              const float* __restrict__ bias, float* __restrict__ C,
              bf16* __restrict__ H1, bf16* __restrict__ L1,
              bf16* __restrict__ H2, bf16* __restrict__ L2,
              int M, int N, int K) {
    extern __shared__ __align__(16) char smem[];
    uint32_t sb = smem_u32(smem);
    int tid = threadIdx.x, lane = tid & 31, w = tid >> 5;
    int wm = w & 3, wn = w >> 2;
    int m0 = blockIdx.x * 128, n0 = blockIdx.y * 128;
    int p = (MODE == 1) ? blockIdx.z : 0;
    int nch = K >> 5;

    float acc[2][8][4] = {};

    auto issue = [&](int c) {
        uint32_t sbase = sb + (c & 1) * G_STAGE;
#pragma unroll
        for (int i = 0; i < 2; i++) {
            int idx = tid + i * 256;
            int r = idx >> 2, g = idx & 3;
            uint32_t dst = (uint32_t)(r * 80 + g * 16);
            size_t aoff, boff;
            if (MODE == 1) {
                int koff = c * 32 + g * 8;
                int m = m0 + r;
                int bb = m >> 10, s = m & 1023;
                int oh = s >> 5, ow = s & 31;
                int xr = (2 * oh + (p >> 1)) * 64 + 2 * ow + (p & 1);
                aoff = ((size_t)(bb * 4096 + xr)) * 512 + koff;
                boff = ((size_t)(p * 512 + n0 + r)) * 512 + koff;
            } else {
                aoff = (size_t)(m0 + r) * K + c * 32 + g * 8;
                boff = (size_t)(n0 + r) * K + c * 32 + g * 8;
            }
            cp16(sbase + G_TA_HI + dst, Ah + aoff);
            cp16(sbase + G_TA_LO + dst, Al + aoff);
            cp16(sbase + G_TB_HI + dst, Bh + boff);
            cp16(sbase + G_TB_LO + dst, Bl + boff);
        }
    };

    uint32_t aoffs = (uint32_t)((wm * 32 + (lane & 15)) * 80 + (lane >> 4) * 16);
    uint32_t boffs = (uint32_t)((wn * 64 + ((lane >> 4) & 1) * 8 + (lane & 7)) * 80
                                + ((lane >> 3) & 1) * 16);

    issue(0); CP_COMMIT();

    for (int c = 0; c < nch; c++) {
        if (c + 1 < nch) { issue(c + 1); CP_COMMIT(); CP_WAIT(1); }
        else             { CP_WAIT(0); }
        __syncthreads();

        uint32_t sbase = sb + (c & 1) * G_STAGE;
#pragma unroll
        for (int ks = 0; ks < 2; ks++) {
            uint32_t ah[2][4], al[2][4];
#pragma unroll
            for (int mi = 0; mi < 2; mi++) {
                ldmat4(ah[mi], sbase + G_TA_HI + aoffs + mi * 1280 + ks * 32);
                ldmat4(al[mi], sbase + G_TA_LO + aoffs + mi * 1280 + ks * 32);
            }
#pragma unroll
            for (int jj = 0; jj < 4; jj++) {
                uint32_t bh4[4], bl4[4];
                ldmat4(bh4, sbase + G_TB_HI + boffs + jj * 1280 + ks * 32);
                ldmat4(bl4, sbase + G_TB_LO + boffs + jj * 1280 + ks * 32);
#pragma unroll
                for (int mi = 0; mi < 2; mi++) {
                    mma_bf16(acc[mi][2 * jj],     ah[mi], bh4[0], bh4[1]);
                    mma_bf16(acc[mi][2 * jj],     ah[mi], bl4[0], bl4[1]);
                    mma_bf16(acc[mi][2 * jj],     al[mi], bh4[0], bh4[1]);
                    mma_bf16(acc[mi][2 * jj + 1], ah[mi], bh4[2], bh4[3]);
                    mma_bf16(acc[mi][2 * jj + 1], ah[mi], bl4[2], bl4[3]);
                    mma_bf16(acc[mi][2 * jj + 1], al[mi], bh4[2], bh4[3]);
                }
            }
        }
        __syncthreads();
    }

#pragma unroll
    for (int mi = 0; mi < 2; mi++) {
        int row = m0 + wm * 32 + mi * 16 + (lane >> 2);
#pragma unroll
        for (int nj = 0; nj < 8; nj++) {
            int col = n0 + wn * 64 + nj * 8 + (lane & 3) * 2;
            if (MODE == 0) {
                float b0 = bias[col], b1 = bias[col + 1];
                float2 v0 = {acc[mi][nj][0] + b0, acc[mi][nj][1] + b1};
                float2 v1 = {acc[mi][nj][2] + b0, acc[mi][nj][3] + b1};
                *(float2*)&C[(size_t)row * N + col] = v0;
                *(float2*)&C[(size_t)(row + 8) * N + col] = v1;
            } else if (MODE == 1) {
                float* out = C + (size_t)p * 2048 * 512;
                float2 v0 = {acc[mi][nj][0], acc[mi][nj][1]};
                float2 v1 = {acc[mi][nj][2], acc[mi][nj][3]};
                *(float2*)&out[(size_t)row * N + col] = v0;
                *(float2*)&out[(size_t)(row + 8) * N + col] = v1;
            } else if (MODE == 2) {
                float b0 = bias[col], b1 = bias[col + 1];
                uint32_t hw, lw;
                split_pack2((acc[mi][nj][0] + b0) * 0.125f,
                            (acc[mi][nj][1] + b1) * 0.125f, hw, lw);
                *(uint32_t*)&H1[(size_t)row * N + col] = hw;
                *(uint32_t*)&L1[(size_t)row * N + col] = lw;
                split_pack2((acc[mi][nj][2] + b0) * 0.125f,
                            (acc[mi][nj][3] + b1) * 0.125f, hw, lw);
                *(uint32_t*)&H1[(size_t)(row + 8) * N + col] = hw;
                *(uint32_t*)&L1[(size_t)(row + 8) * N + col] = lw;
            } else {  // MODE 3: kv
                float b0 = bias[col], b1 = bias[col + 1];
                bf16* Hd = (col < 512) ? H1 : H2;
                bf16* Ld = (col < 512) ? L1 : L2;
                int c2 = col & 511;
                uint32_t hw, lw;
                split_pack2(acc[mi][nj][0] + b0, acc[mi][nj][1] + b1, hw, lw);
                *(uint32_t*)&Hd[(size_t)row * 512 + c2] = hw;
                *(uint32_t*)&Ld[(size_t)row * 512 + c2] = lw;
                split_pack2(acc[mi][nj][2] + b0, acc[mi][nj][3] + b1, hw, lw);
                *(uint32_t*)&Hd[(size_t)(row + 8) * 512 + c2] = hw;
                *(uint32_t*)&Ld[(size_t)(row + 8) * 512 + c2] = lw;
            }
        }
    }
}

// ===========================================================================
// Sum conv partials + bias, LayerNorm, write bf16 hi/lo directly
// ===========================================================================
__global__ void ln_fuse_kernel(const float* __restrict__ part,
                               const float* __restrict__ bsr,
                               const float* __restrict__ gamma,
                               const float* __restrict__ beta,
                               bf16* __restrict__ xsh, bf16* __restrict__ xsl) {
    __shared__ float red[256];
    __shared__ float s_mean, s_inv;
    const size_t RS = (size_t)2048 * 512;
    int t = threadIdx.x;
    size_t ro = (size_t)blockIdx.x * 512;

    float v0 = part[ro + t] + part[RS + ro + t] + part[2 * RS + ro + t] +
               part[3 * RS + ro + t] + bsr[t];
    int t2 = t + 256;
    float v1 = part[ro + t2] + part[RS + ro + t2] + part[2 * RS + ro + t2] +
               part[3 * RS + ro + t2] + bsr[t2];

    red[t] = v0 + v1;
    __syncthreads();
    for (int off = 128; off; off >>= 1) {
        if (t < off) red[t] += red[t + off];
        __syncthreads();
    }
    if (t == 0) s_mean = red[0] * (1.f / 512.f);
    __syncthreads();
    float mean = s_mean;
    float d0 = v0 - mean, d1 = v1 - mean;
    red[t] = d0 * d0 + d1 * d1;
    __syncthreads();
    for (int off = 128; off; off >>= 1) {
        if (t < off) red[t] += red[t + off];
        __syncthreads();
    }
    if (t == 0) s_inv = rsqrtf(red[0] * (1.f / 512.f) + LN_EPS);
    __syncthreads();
    float inv = s_inv;
    float y0 = d0 * inv * gamma[t]  + beta[t];
    float y1 = d1 * inv * gamma[t2] + beta[t2];
    split2(y0, xsh[ro + t],  xsl[ro + t]);
    split2(y1, xsh[ro + t2], xsl[ro + t2]);
}

// ===========================================================================
// Flash attention, mma.sync bf16x3, double-buffered KV with Q-region overlay.
// smem total 72 KB -> 2 CTAs/SM. Region A [0,36864) holds Q during prologue,
// then becomes KV stage for odd tiles; region B [36864,73728) = even tiles.
// ===========================================================================
#define P_QH  0
#define P_QL  18432
#define P_STG 36864
#define S_KH  0
#define S_KL  9216
#define S_VH  18432
#define S_VL  27648
#define A_SMEM 73728

__global__ __launch_bounds__(256, 2)
void attn_mma(const bf16* __restrict__ qh, const bf16* __restrict__ ql,
              const bf16* __restrict__ kh, const bf16* __restrict__ kl,
              const bf16* __restrict__ vh, const bf16* __restrict__ vl,
              bf16* __restrict__ aoh, bf16* __restrict__ aol) {
    extern __shared__ __align__(16) char smem[];
    uint32_t sb = smem_u32(smem);
    int tid = threadIdx.x, lane = tid & 31, w = tid >> 5;
    int b = blockIdx.z, h = blockIdx.y;
    int q0 = blockIdx.x * 128;

    size_t kvbase = ((size_t)b * 1024) * 512 + h * 64;

    // stage(t): even t -> region B (P_STG), odd t -> region A (0, ex-Q)
    auto issue_kv = [&](int t) {
        uint32_t su = sb + ((t & 1) ? 0u : (uint32_t)P_STG);
#pragma unroll
        for (int i = 0; i < 2; i++) {
            int idx = tid + i * 256;
            int r = idx >> 3, g = idx & 7;
            uint32_t dst = (uint32_t)(r * 144 + g * 16);
            size_t src = kvbase + (size_t)(t * 64 + r) * 512 + g * 8;
            cp16(su + S_KH + dst, kh + src);
            cp16(su + S_KL + dst, kl + src);
            cp16(su + S_VH + dst, vh + src);
            cp16(su + S_VL + dst, vl + src);
        }
    };

    // prefetch KV tile 0 into region B while loading Q into region A
    issue_kv(0); CP_COMMIT();

    size_t qbase = ((size_t)(b * 4096 + q0)) * 512 + h * 64;
#pragma unroll
    for (int i = 0; i < 4; i++) {
        int idx = tid + i * 256;
        int r = idx >> 3, g = idx & 7;
        uint32_t dst = (uint32_t)(r * 144 + g * 16);
        size_t src = qbase + (size_t)r * 512 + g * 8;
        *(uint4*)(smem + P_QH + dst) = *(const uint4*)(qh + src);
        *(uint4*)(smem + P_QL + dst) = *(const uint4*)(ql + src);
    }
    __syncthreads();

    // hoist Q fragments, then block-sync before region A is reused for KV
    uint32_t qf_h[4][4], qf_l[4][4];
    uint32_t qoffs = (uint32_t)((w * 16 + (lane & 15)) * 144 + (lane >> 4) * 16);
#pragma unroll
    for (int ks = 0; ks < 4; ks++) {
        ldmat4(qf_h[ks], sb + P_QH + qoffs + ks * 32);
        ldmat4(qf_l[ks], sb + P_QL + qoffs + ks * 32);
    }
    __syncthreads();

    float o[8][4] = {};
    float mrun0 = -3.0e38f, mrun1 = -3.0e38f, lrun0 = 0.f, lrun1 = 0.f;

    uint32_t koffs = (uint32_t)((((lane >> 4) & 1) * 8 + (lane & 7)) * 144
                                + ((lane >> 3) & 1) * 16);
    uint32_t voffs = (uint32_t)((((lane >> 3) & 1) * 8 + (lane & 7)) * 144
                                + (lane >> 4) * 16);

    for (int t = 0; t < 16; t++) {
        if (t + 1 < 16) { issue_kv(t + 1); CP_COMMIT(); CP_WAIT(1); }
        else            { CP_WAIT(0); }
        __syncthreads();

        uint32_t stg = sb + ((t & 1) ? 0u : (uint32_t)P_STG);

        // ---- S = Q K^T ----
        float s[8][4] = {};
#pragma unroll
        for (int ks = 0; ks < 4; ks++) {
#pragma unroll
            for (int jj = 0; jj < 4; jj++) {
                uint32_t bh4[4], bl4[4];
                ldmat4(bh4, stg + S_KH + koffs + jj * 2304 + ks * 32);
                ldmat4(bl4, stg + S_KL + koffs + jj * 2304 + ks * 32);
                mma_bf16(s[2 * jj],     qf_h[ks], bh4[0], bh4[1]);
                mma_bf16(s[2 * jj],     qf_h[ks], bl4[0], bl4[1]);
                mma_bf16(s[2 * jj],     qf_l[ks], bh4[0], bh4[1]);
                mma_bf16(s[2 * jj + 1], qf_h[ks], bh4[2], bh4[3]);
                mma_bf16(s[2 * jj + 1], qf_h[ks], bl4[2], bl4[3]);
                mma_bf16(s[2 * jj + 1], qf_l[ks], bh4[2], bh4[3]);
            }
        }

        // ---- online softmax ----
        float tm0 = -3.0e38f, tm1 = -3.0e38f;
#pragma unroll
        for (int nj = 0; nj < 8; nj++) {
            tm0 = fmaxf(tm0, fmaxf(s[nj][0], s[nj][1]));
            tm1 = fmaxf(tm1, fmaxf(s[nj][2], s[nj][3]));
        }
        tm0 = fmaxf(tm0, __shfl_xor_sync(0xffffffffu, tm0, 1));
        tm0 = fmaxf(tm0, __shfl_xor_sync(0xffffffffu, tm0, 2));
        tm1 = fmaxf(tm1, __shfl_xor_sync(0xffffffffu, tm1, 1));
        tm1 = fmaxf(tm1, __shfl_xor_sync(0xffffffffu, tm1, 2));
        float mn0 = fmaxf(mrun0, tm0), mn1 = fmaxf(mrun1, tm1);
        float corr0 = exp2f((mrun0 - mn0) * LOG2E);
        float corr1 = exp2f((mrun1 - mn1) * LOG2E);
        mrun0 = mn0; mrun1 = mn1;
        float ls0 = 0.f, ls1 = 0.f;
#pragma unroll
        for (int nj = 0; nj < 8; nj++) {
            s[nj][0] = exp2f((s[nj][0] - mn0) * LOG2E);
            s[nj][1] = exp2f((s[nj][1] - mn0) * LOG2E);
            s[nj][2] = exp2f((s[nj][2] - mn1) * LOG2E);
            s[nj][3] = exp2f((s[nj][3] - mn1) * LOG2E);
            ls0 += s[nj][0] + s[nj][1];
            ls1 += s[nj][2] + s[nj][3];
        }
        ls0 += __shfl_xor_sync(0xffffffffu, ls0, 1);
        ls0 += __shfl_xor_sync(0xffffffffu, ls0, 2);
        ls1 += __shfl_xor_sync(0xffffffffu, ls1, 1);
        ls1 += __shfl_xor_sync(0xffffffffu, ls1, 2);
        lrun0 = lrun0 * corr0 + ls0;
        lrun1 = lrun1 * corr1 + ls1;
#pragma unroll
        for (int nd = 0; nd < 8; nd++) {
            o[nd][0] *= corr0; o[nd][1] *= corr0;
            o[nd][2] *= corr1; o[nd][3] *= corr1;
        }

        // ---- O += P V ----
#pragma unroll
        for (int j = 0; j < 4; j++) {
            float* pa = s[2 * j];
            float* pb = s[2 * j + 1];
            bf16 h00, h01, h02, h03, h10, h11, h12, h13;
            bf16 l00, l01, l02, l03, l10, l11, l12, l13;
            split2(pa[0], h00, l00); split2(pa[1], h01, l01);
            split2(pa[2], h02, l02); split2(pa[3], h03, l03);
            split2(pb[0], h10, l10); split2(pb[1], h11, l11);
            split2(pb[2], h12, l12); split2(pb[3], h13, l13);
            uint32_t pah[4], pal[4];
            pah[0] = pack_bf2(h00, h01);
            pah[1] = pack_bf2(h02, h03);
            pah[2] = pack_bf2(h10, h11);
            pah[3] = pack_bf2(h12, h13);
            pal[0] = pack_bf2(l00, l01);
            pal[1] = pack_bf2(l02, l03);
            pal[2] = pack_bf2(l10, l11);
            pal[3] = pack_bf2(l12, l13);
#pragma unroll
            for (int nd2 = 0; nd2 < 4; nd2++) {
                uint32_t vh4[4], vl4[4];
                ldmat4t(vh4, stg + S_VH + voffs + j * 2304 + nd2 * 32);
                ldmat4t(vl4, stg + S_VL + voffs + j * 2304 + nd2 * 32);
                mma_bf16(o[2 * nd2],     pah, vh4[0], vh4[1]);
                mma_bf16(o[2 * nd2],     pah, vl4[0], vl4[1]);
                mma_bf16(o[2 * nd2],     pal, vh4[0], vh4[1]);
                mma_bf16(o[2 * nd2 + 1], pah, vh4[2], vh4[3]);
                mma_bf16(o[2 * nd2 + 1], pah, vl4[2], vl4[3]);
                mma_bf16(o[2 * nd2 + 1], pal, vh4[2], vh4[3]);
            }
        }
        __syncthreads();
    }

    // ---- epilogue: write bf16 hi/lo directly ----
    float inv0 = 1.f / lrun0, inv1 = 1.f / lrun1;
    int r0 = q0 + w * 16 + (lane >> 2);
    size_t obase = ((size_t)(b * 4096)) * 512 + h * 64;
#pragma unroll
    for (int nd = 0; nd < 8; nd++) {
        int col = nd * 8 + (lane & 3) * 2;
        uint32_t hw, lw;
        split_pack2(o[nd][0] * inv0, o[nd][1] * inv0, hw, lw);
        *(uint32_t*)&aoh[obase + (size_t)r0 * 512 + col] = hw;
        *(uint32_t*)&aol[obase + (size_t)r0 * 512 + col] = lw;
        split_pack2(o[nd][2] * inv1, o[nd][3] * inv1, hw, lw);
        *(uint32_t*)&aoh[obase + (size_t)(r0 + 8) * 512 + col] = hw;
        *(uint32_t*)&aol[obase + (size_t)(r0 + 8) * 512 + col] = lw;
    }
}

// ===========================================================================
// Launch
// ===========================================================================
extern "C" void kernel_launch(void* const* d_in, const int* in_sizes, int n_in,
                              void* d_out, int out_size) {
    (void)in_sizes; (void)n_in; (void)out_size;

    const float* x     = (const float*)d_in[0];
    const float* Wq    = (const float*)d_in[1];
    const float* bq    = (const float*)d_in[2];
    const float* Wkv   = (const float*)d_in[3];
    const float* bkv   = (const float*)d_in[4];
    const float* Wproj = (const float*)d_in[5];
    const float* bproj = (const float*)d_in[6];
    const float* Aq    = (const float*)d_in[7];
    const float* Bq    = (const float*)d_in[8];
    const float* Av    = (const float*)d_in[9];
    const float* Bv    = (const float*)d_in[10];
    const float* Wsr   = (const float*)d_in[11];
    const float* bsr   = (const float*)d_in[12];
    const float* gamma = (const float*)d_in[13];
    const float* beta  = (const float*)d_in[14];
    float* out = (float*)d_out;

    float *convp;
    bf16 *xhi, *xlo, *xshi, *xslo, *aohi, *aolo, *qhi, *qlo;
    bf16 *khi, *klo, *vhi, *vlo;
    bf16 *WqTh, *WqTl, *WkvTh, *WkvTl, *WpTh, *WpTl, *WsrTh, *WsrTl;
    cudaGetSymbolAddress((void**)&convp, g_convp);
    cudaGetSymbolAddress((void**)&xhi,   g_xhi);
    cudaGetSymbolAddress((void**)&xlo,   g_xlo);
    cudaGetSymbolAddress((void**)&xshi,  g_xshi);
    cudaGetSymbolAddress((void**)&xslo,  g_xslo);
    cudaGetSymbolAddress((void**)&aohi,  g_aohi);
    cudaGetSymbolAddress((void**)&aolo,  g_aolo);
    cudaGetSymbolAddress((void**)&qhi,   g_qhi);
    cudaGetSymbolAddress((void**)&qlo,   g_qlo);
    cudaGetSymbolAddress((void**)&khi,   g_khi);
    cudaGetSymbolAddress((void**)&klo,   g_klo);
    cudaGetSymbolAddress((void**)&vhi,   g_vhi);
    cudaGetSymbolAddress((void**)&vlo,   g_vlo);
    cudaGetSymbolAddress((void**)&WqTh,  g_WqTh);
    cudaGetSymbolAddress((void**)&WqTl,  g_WqTl);
    cudaGetSymbolAddress((void**)&WkvTh, g_WkvTh);
    cudaGetSymbolAddress((void**)&WkvTl, g_WkvTl);
    cudaGetSymbolAddress((void**)&WpTh,  g_WpTh);
    cudaGetSymbolAddress((void**)&WpTl,  g_WpTl);
    cudaGetSymbolAddress((void**)&WsrTh, g_WsrTh);
    cudaGetSymbolAddress((void**)&WsrTl, g_WsrTl);

    cudaFuncSetAttribute(gemm_mma<0>, cudaFuncAttributeMaxDynamicSharedMemorySize, G_SMEM);
    cudaFuncSetAttribute(gemm_mma<1>, cudaFuncAttributeMaxDynamicSharedMemorySize, G_SMEM);
    cudaFuncSetAttribute(gemm_mma<2>, cudaFuncAttributeMaxDynamicSharedMemorySize, G_SMEM);
    cudaFuncSetAttribute(gemm_mma<3>, cudaFuncAttributeMaxDynamicSharedMemorySize, G_SMEM);
    cudaFuncSetAttribute(attn_mma, cudaFuncAttributeMaxDynamicSharedMemorySize, A_SMEM);

    // weight prep (tiled transposes)
    dim3 tb(32, 8);
    prep_wqT_kernel<<<dim3(16, 16), tb>>>(Wq, Aq, Bq, WqTh, WqTl);
    prep_wkvT_kernel<<<dim3(32, 16), tb>>>(Wkv, Av, Bv, WkvTh, WkvTl);
    prep_wpT_kernel<<<dim3(16, 16), tb>>>(Wproj, WpTh, WpTl);
    prep_wsrT_kernel<<<dim3(16, 16, 4), tb>>>(Wsr, WsrTh, WsrTl);

    // split x
    split_kernel<<<4096, 256>>>(x, xhi, xlo);

    // q GEMM -> qhi/qlo (scaled)   (8192 x 512 x 512)
    gemm_mma<2><<<dim3(64, 4), 256, G_SMEM>>>(xhi, xlo, WqTh, WqTl, bq,
                                              nullptr, qhi, qlo, nullptr, nullptr,
                                              8192, 512, 512);

    // conv split-K by patch -> partials   (2048 x 512 x 512 per patch)
    gemm_mma<1><<<dim3(16, 4, 4), 256, G_SMEM>>>(xhi, xlo, WsrTh, WsrTl, nullptr,
                                                 convp, nullptr, nullptr, nullptr, nullptr,
                                                 2048, 512, 512);

    // sum partials + bias + LN -> xshi/xslo
    ln_fuse_kernel<<<2048, 256>>>(convp, bsr, gamma, beta, xshi, xslo);

    // kv GEMM -> k/v hi/lo   (2048 x 1024 x 512)
    gemm_mma<3><<<dim3(16, 8), 256, G_SMEM>>>(xshi, xslo, WkvTh, WkvTl, bkv,
                                              nullptr, khi, klo, vhi, vlo,
                                              2048, 1024, 512);

    // attention -> aohi/aolo
    attn_mma<<<dim3(32, 8, 2), 256, A_SMEM>>>(qhi, qlo, khi, klo, vhi, vlo, aohi, aolo);

    // proj -> out   (8192 x 512 x 512)
    gemm_mma<0><<<dim3(64, 4), 256, G_SMEM>>>(aohi, aolo, WpTh, WpTl, bproj,
                                              out, nullptr, nullptr, nullptr, nullptr,
                                              8192, 512, 512);
}